// round 6
// baseline (speedup 1.0000x reference)
#include <cuda_runtime.h>
#include <cuda_bf16.h>
#include <cuda_fp16.h>
#include <math_constants.h>
#include <stdint.h>

#define NN 25000
#define EE 250000
#define HH 4
#define DD 64
#define HD 256   // H*D

// ---------------- scratch (device globals; no allocation allowed) -------------
__device__ __half g_feat16[NN * HD];   // x @ W for current layer, fp16
__device__ float  g_h[NN * HD];        // layer output (next layer input), fp32
__device__ __half g_hh[NN * HD];       // final layer output, fp16 (score input)
__device__ float g_elp[2 * NN * HH];
__device__ float g_erp[2 * NN * HH];
__device__ int g_cnt[NN];
__device__ int g_off[NN + 1];
__device__ int g_cur[NN];
__device__ int g_csr_src[EE];

// ---------------- helpers ----------------------------------------------------
__device__ __forceinline__ void mma_tf32(float* d, const uint32_t* a, const uint32_t* b) {
    asm volatile(
        "mma.sync.aligned.m16n8k8.row.col.f32.tf32.tf32.f32 "
        "{%0,%1,%2,%3}, {%4,%5,%6,%7}, {%8,%9}, {%0,%1,%2,%3};"
        : "+f"(d[0]), "+f"(d[1]), "+f"(d[2]), "+f"(d[3])
        : "r"(a[0]), "r"(a[1]), "r"(a[2]), "r"(a[3]), "r"(b[0]), "r"(b[1]));
}

__device__ __forceinline__ uint32_t f2tf32(float f) {
    uint32_t r;
    asm("cvt.rna.tf32.f32 %0, %1;" : "=r"(r) : "f"(f));
    return r;
}

// ---------------- CSR build ---------------------------------------------------
__global__ __launch_bounds__(256) void csr_hist_kernel(const int* __restrict__ dst) {
    int i = blockIdx.x * blockDim.x + threadIdx.x;
    if (i < EE) atomicAdd(&g_cnt[dst[i]], 1);
}

__global__ __launch_bounds__(1024) void csr_scan_kernel() {
    __shared__ int part[1024];
    const int tid = threadIdx.x;
    const int base = tid * 25;
    int loc[25];
    int s = 0;
#pragma unroll
    for (int j = 0; j < 25; j++) {
        int idx = base + j;
        int c = (idx < NN) ? g_cnt[idx] : 0;
        loc[j] = s;
        s += c;
    }
    part[tid] = s;
    __syncthreads();
    for (int off = 1; off < 1024; off <<= 1) {
        int v = (tid >= off) ? part[tid - off] : 0;
        __syncthreads();
        part[tid] += v;
        __syncthreads();
    }
    const int excl = (tid == 0) ? 0 : part[tid - 1];
#pragma unroll
    for (int j = 0; j < 25; j++) {
        int idx = base + j;
        if (idx < NN) {
            int o = excl + loc[j];
            g_off[idx] = o;
            g_cur[idx] = o;
        }
    }
    if (tid == 0) g_off[NN] = EE;
}

__global__ __launch_bounds__(256) void csr_scatter_kernel(const int* __restrict__ src,
                                                          const int* __restrict__ dst) {
    int e = blockIdx.x * blockDim.x + threadIdx.x;
    if (e >= EE) return;
    int slot = atomicAdd(&g_cur[dst[e]], 1);
    g_csr_src[slot] = src[e];
}

// ---------------- TF32 GEMM + fused el/er + fp16 out --------------------------
// Block 128x128, BK=16, 8 warps (2m x 4n), warp 64x32 (4x4 m16n8 atoms).
// Fragment-ready smem layouts:
//  A: 16 frags (rg 0..7, kg 0..1) of 128 words; lane slot = g*4 + (c^(g>>1)),
//     4 contiguous words per lane (one LDS.128 per frag load).
//  B: 32 frags (kg 0..1, ng 0..15) of 66 words (2 pad); lane slot holds (b0,b1)
//     as uint2 (one LDS.64 per n8 frag).
// Double-buffered, one __syncthreads per k-tile.
#define AS_STAGE 2048   // 16 * 128 words
#define BS_STAGE 2112   // 32 * 66 words

__global__ __launch_bounds__(256, 2) void gemm_fused(const float* __restrict__ A,
                                                     const float* __restrict__ B,
                                                     const float* __restrict__ alp,
                                                     const float* __restrict__ arp,
                                                     __half* __restrict__ C16) {
    __shared__ __align__(16) uint32_t As[2 * AS_STAGE];
    __shared__ __align__(16) uint32_t Bs[2 * BS_STAGE];

    const int tid = threadIdx.x;
    const int bm = blockIdx.x * 128;
    const int bn = blockIdx.y * 128;
    const int lane = tid & 31;
    const int wid = tid >> 5;
    const int wm = (wid >> 2) * 64;
    const int wn = (wid & 3) * 32;
    const int g  = lane >> 2;
    const int c  = lane & 3;
    const int c2 = c * 2;
    // consumer fragment slot (same swizzle as producer writes)
    const int slotA = g * 4 + ((c ^ (g >> 1)) & 3);   // uint4 slot within A frag
    const int slotB = slotA;                           // uint2 slot within B frag

    float acc[4][4][4];
#pragma unroll
    for (int i = 0; i < 4; i++)
#pragma unroll
        for (int j = 0; j < 4; j++)
#pragma unroll
            for (int t = 0; t < 4; t++) acc[i][j][t] = 0.f;

    // ---- A loader mapping: arow = tid&127, kg = tid>>7 ----
    const int arow = tid & 127;
    const int lkg  = tid >> 7;           // 0/1
    const int agr  = bm + arow;
    const bool aval = agr < NN;
    const int a_rg = arow >> 4;
    const int a_g  = arow & 7;
    const int a_hi = (arow >> 3) & 1;
    // per-kc store offsets within frag
    int a_store[8];
#pragma unroll
    for (int kc = 0; kc < 8; kc++) {
        int cc = kc & 3, khi = kc >> 2;
        int sl = a_g * 4 + ((cc ^ (a_g >> 1)) & 3);
        a_store[kc] = (a_rg * 2 + lkg) * 128 + sl * 4 + a_hi + 2 * khi;
    }
    // ---- B loader mapping: bk = tid>>4, ng = tid&15 ----
    const int bk  = tid >> 4;
    const int bng = tid & 15;
    const int b_kg  = bk >> 3;
    const int b_c   = bk & 3;
    const int b_khi = (bk >> 2) & 1;
    int b_store[8];
#pragma unroll
    for (int t = 0; t < 8; t++) {
        int sl = t * 4 + ((b_c ^ (t >> 1)) & 3);
        b_store[t] = (b_kg * 16 + bng) * 66 + sl * 2 + b_khi;
    }

    float pa[8], pb[8];

    // ---- prefetch stage 0 ----
    {
        if (aval) {
            const float4* s = (const float4*)(A + agr * 256 + lkg * 8);
            float4 v0 = s[0], v1 = s[1];
            pa[0]=v0.x; pa[1]=v0.y; pa[2]=v0.z; pa[3]=v0.w;
            pa[4]=v1.x; pa[5]=v1.y; pa[6]=v1.z; pa[7]=v1.w;
        } else {
#pragma unroll
            for (int q = 0; q < 8; q++) pa[q] = 0.f;
        }
        const float4* s = (const float4*)(B + bk * 256 + bn + bng * 8);
        float4 v0 = s[0], v1 = s[1];
        pb[0]=v0.x; pb[1]=v0.y; pb[2]=v0.z; pb[3]=v0.w;
        pb[4]=v1.x; pb[5]=v1.y; pb[6]=v1.z; pb[7]=v1.w;
    }
    // store stage 0 to buf 0
    {
#pragma unroll
        for (int q = 0; q < 8; q++) As[a_store[q]] = f2tf32(pa[q]);
#pragma unroll
        for (int q = 0; q < 8; q++) Bs[b_store[q]] = f2tf32(pb[q]);
    }
    __syncthreads();

#pragma unroll 2
    for (int kt = 0; kt < 16; kt++) {
        const int cur = kt & 1;
        const uint32_t* __restrict__ Ab = As + cur * AS_STAGE;
        const uint32_t* __restrict__ Bb = Bs + cur * BS_STAGE;

        // prefetch next tile (global -> regs)
        if (kt < 15) {
            const int kk = (kt + 1) * 16;
            if (aval) {
                const float4* s = (const float4*)(A + agr * 256 + kk + lkg * 8);
                float4 v0 = s[0], v1 = s[1];
                pa[0]=v0.x; pa[1]=v0.y; pa[2]=v0.z; pa[3]=v0.w;
                pa[4]=v1.x; pa[5]=v1.y; pa[6]=v1.z; pa[7]=v1.w;
            }
            const float4* s = (const float4*)(B + (kk + bk) * 256 + bn + bng * 8);
            float4 v0 = s[0], v1 = s[1];
            pb[0]=v0.x; pb[1]=v0.y; pb[2]=v0.z; pb[3]=v0.w;
            pb[4]=v1.x; pb[5]=v1.y; pb[6]=v1.z; pb[7]=v1.w;
        }

        // compute: 2 k8 steps from frag-ready smem
#pragma unroll
        for (int kg = 0; kg < 2; kg++) {
            uint32_t bfr[4][2];
#pragma unroll
            for (int j = 0; j < 4; j++) {
                const int f = kg * 16 + (wn >> 3) + j;
                uint2 bv = *(const uint2*)(Bb + f * 66 + slotB * 2);
                bfr[j][0] = bv.x; bfr[j][1] = bv.y;
            }
#pragma unroll
            for (int i = 0; i < 4; i++) {
                const int f = ((wm >> 4) + i) * 2 + kg;
                uint4 av = *(const uint4*)(Ab + f * 128 + slotA * 4);
                uint32_t afr[4] = {av.x, av.y, av.z, av.w};
#pragma unroll
                for (int j = 0; j < 4; j++) mma_tf32(acc[i][j], afr, bfr[j]);
            }
        }

        // store next tile into the other buffer (safe: all warps passed the
        // last sync, so nobody is still reading buf 1-cur)
        if (kt < 15) {
            uint32_t* An = As + (1 - cur) * AS_STAGE;
            uint32_t* Bn = Bs + (1 - cur) * BS_STAGE;
#pragma unroll
            for (int q = 0; q < 8; q++) An[a_store[q]] = f2tf32(pa[q]);
#pragma unroll
            for (int q = 0; q < 8; q++) Bn[b_store[q]] = f2tf32(pb[q]);
        }
        __syncthreads();
    }

    // ---- epilogue: fp16 feat store + fused el/er partials ----
    const int colbase = bn + wn;
    const int hh_ = colbase >> 6;
    const int q_  = (colbase >> 5) & 1;
    float alv[4][2], arv[4][2];
#pragma unroll
    for (int j = 0; j < 4; j++) {
        int col = colbase + j * 8 + c2;
        alv[j][0] = alp[col];     alv[j][1] = alp[col + 1];
        arv[j][0] = arp[col];     arv[j][1] = arp[col + 1];
    }

#pragma unroll
    for (int i = 0; i < 4; i++) {
        const int r = bm + wm + i * 16 + g;
        float pel0 = 0.f, per0 = 0.f, pel1 = 0.f, per1 = 0.f;
#pragma unroll
        for (int j = 0; j < 4; j++) {
            const int col = colbase + j * 8 + c2;
            pel0 += acc[i][j][0] * alv[j][0] + acc[i][j][1] * alv[j][1];
            per0 += acc[i][j][0] * arv[j][0] + acc[i][j][1] * arv[j][1];
            pel1 += acc[i][j][2] * alv[j][0] + acc[i][j][3] * alv[j][1];
            per1 += acc[i][j][2] * arv[j][0] + acc[i][j][3] * arv[j][1];
            __half2 h01 = __floats2half2_rn(acc[i][j][0], acc[i][j][1]);
            __half2 h23 = __floats2half2_rn(acc[i][j][2], acc[i][j][3]);
            if (r < NN)     *(__half2*)(C16 + r * 256 + col)       = h01;
            if (r + 8 < NN) *(__half2*)(C16 + (r + 8) * 256 + col) = h23;
        }
#pragma unroll
        for (int o = 1; o <= 2; o <<= 1) {
            pel0 += __shfl_xor_sync(0xffffffffu, pel0, o);
            per0 += __shfl_xor_sync(0xffffffffu, per0, o);
            pel1 += __shfl_xor_sync(0xffffffffu, pel1, o);
            per1 += __shfl_xor_sync(0xffffffffu, per1, o);
        }
        if (c == 0) {
            if (r < NN) {
                g_elp[q_ * (NN * HH) + r * HH + hh_] = pel0;
                g_erp[q_ * (NN * HH) + r * HH + hh_] = per0;
            }
            if (r + 8 < NN) {
                g_elp[q_ * (NN * HH) + (r + 8) * HH + hh_] = pel1;
                g_erp[q_ * (NN * HH) + (r + 8) * HH + hh_] = per1;
            }
        }
    }
}

// ---------------- fused edge softmax + aggregation + bias/relu (single pass) --
template <bool LAST>
__global__ __launch_bounds__(256) void fused_edge_kernel(const float* __restrict__ b) {
    const int n = (blockIdx.x * blockDim.x + threadIdx.x) >> 5;
    const int lane = threadIdx.x & 31;
    if (n >= NN) return;

    const int off = g_off[n];
    const int deg = g_off[n + 1] - off;
    const int h = lane >> 3;

    const float erh = g_erp[n * HH + h] + g_erp[NN * HH + n * HH + h];

    float acc[8];
#pragma unroll
    for (int j = 0; j < 8; j++) acc[j] = 0.f;
    float ssum = 0.f;

    for (int i = 0; i < deg; i++) {
        const int s = g_csr_src[off + i];
        float e = g_elp[s * HH + h] + g_elp[NN * HH + s * HH + h] + erh;
        e = e > 0.f ? e : 0.2f * e;
        const float a = __expf(e);
        ssum += a;
        const uint4 p = *(const uint4*)(g_feat16 + s * HD + lane * 8);
        const __half2* ph = (const __half2*)&p;
        float2 f0 = __half22float2(ph[0]);
        float2 f1 = __half22float2(ph[1]);
        float2 f2 = __half22float2(ph[2]);
        float2 f3 = __half22float2(ph[3]);
        acc[0] += a * f0.x; acc[1] += a * f0.y;
        acc[2] += a * f1.x; acc[3] += a * f1.y;
        acc[4] += a * f2.x; acc[5] += a * f2.y;
        acc[6] += a * f3.x; acc[7] += a * f3.y;
    }
    const float inv = (ssum > 0.f) ? (1.f / ssum) : 0.f;

    const float4 b0 = *(const float4*)(b + lane * 8);
    const float4 b1 = *(const float4*)(b + lane * 8 + 4);
    float o0 = fmaxf(acc[0] * inv + b0.x, 0.f);
    float o1 = fmaxf(acc[1] * inv + b0.y, 0.f);
    float o2 = fmaxf(acc[2] * inv + b0.z, 0.f);
    float o3 = fmaxf(acc[3] * inv + b0.w, 0.f);
    float o4 = fmaxf(acc[4] * inv + b1.x, 0.f);
    float o5 = fmaxf(acc[5] * inv + b1.y, 0.f);
    float o6 = fmaxf(acc[6] * inv + b1.z, 0.f);
    float o7 = fmaxf(acc[7] * inv + b1.w, 0.f);

    if (LAST) {
        __half2 p0 = __floats2half2_rn(o0, o1);
        __half2 p1 = __floats2half2_rn(o2, o3);
        __half2 p2 = __floats2half2_rn(o4, o5);
        __half2 p3 = __floats2half2_rn(o6, o7);
        uint4 pk;
        pk.x = *(uint32_t*)&p0; pk.y = *(uint32_t*)&p1;
        pk.z = *(uint32_t*)&p2; pk.w = *(uint32_t*)&p3;
        ((uint4*)(g_hh + n * HD))[lane] = pk;
    } else {
        float4* o = (float4*)(g_h + n * HD + lane * 8);
        o[0] = make_float4(o0, o1, o2, o3);
        o[1] = make_float4(o4, o5, o6, o7);
    }
}

// ---------------- final dot scores (fp16 gather, fp32 accumulate) --------------
__global__ __launch_bounds__(256) void score_kernel(const int* __restrict__ src,
                                                    const int* __restrict__ dst,
                                                    const int* __restrict__ nsrc,
                                                    const int* __restrict__ ndst,
                                                    float* __restrict__ out) {
    int w = (blockIdx.x * blockDim.x + threadIdx.x) >> 5;
    int lane = threadIdx.x & 31;
    if (w >= 2 * EE) return;
    bool pos = w < EE;
    int e = pos ? w : w - EE;
    int uN = pos ? src[e] : nsrc[e];
    int vN = pos ? dst[e] : ndst[e];

    uint4 up = ((const uint4*)(g_hh + uN * HD))[lane];
    uint4 vp = ((const uint4*)(g_hh + vN * HD))[lane];
    float2 u0 = __half22float2(*(__half2*)&up.x), v0 = __half22float2(*(__half2*)&vp.x);
    float2 u1 = __half22float2(*(__half2*)&up.y), v1 = __half22float2(*(__half2*)&vp.y);
    float2 u2 = __half22float2(*(__half2*)&up.z), v2 = __half22float2(*(__half2*)&vp.z);
    float2 u3 = __half22float2(*(__half2*)&up.w), v3 = __half22float2(*(__half2*)&vp.w);
    float d = u0.x * v0.x + u0.y * v0.y + u1.x * v1.x + u1.y * v1.y +
              u2.x * v2.x + u2.y * v2.y + u3.x * v3.x + u3.y * v3.y;
#pragma unroll
    for (int off = 4; off >= 1; off >>= 1) d += __shfl_down_sync(0xffffffffu, d, off, 8);
    if ((lane & 7) == 0) {
        int h = lane >> 3;
        out[(pos ? 0 : EE * HH) + e * HH + h] = d;
    }
}

// ---------------- launch -------------------------------------------------------
extern "C" void kernel_launch(void* const* d_in, const int* in_sizes, int n_in,
                              void* d_out, int out_size) {
    const float* x    = (const float*)d_in[0];
    const int* src    = (const int*)d_in[1];
    const int* dst    = (const int*)d_in[2];
    const int* nsrc   = (const int*)d_in[3];
    const int* ndst   = (const int*)d_in[4];
    const float* W[3]  = {(const float*)d_in[5], (const float*)d_in[9],  (const float*)d_in[13]};
    const float* al[3] = {(const float*)d_in[6], (const float*)d_in[10], (const float*)d_in[14]};
    const float* ar[3] = {(const float*)d_in[7], (const float*)d_in[11], (const float*)d_in[15]};
    const float* bb[3] = {(const float*)d_in[8], (const float*)d_in[12], (const float*)d_in[16]};
    float* out = (float*)d_out;

    float* hbuf = nullptr;
    cudaGetSymbolAddress((void**)&hbuf, g_h);
    __half* featbuf = nullptr;
    cudaGetSymbolAddress((void**)&featbuf, g_feat16);
    int* cntbuf = nullptr;
    cudaGetSymbolAddress((void**)&cntbuf, g_cnt);

    // --- CSR build (dst constant across layers) ---
    cudaMemsetAsync(cntbuf, 0, NN * sizeof(int));
    csr_hist_kernel<<<(EE + 255) / 256, 256>>>(dst);
    csr_scan_kernel<<<1, 1024>>>();
    csr_scatter_kernel<<<(EE + 255) / 256, 256>>>(src, dst);

    dim3 gemm_grid((NN + 127) / 128, 2);
    const int node_blocks  = (NN * 32 + 255) / 256;
    const int score_blocks = (2 * EE * 32 + 255) / 256;

    const float* layer_in = x;
    for (int l = 0; l < 3; l++) {
        gemm_fused<<<gemm_grid, 256>>>(layer_in, W[l], al[l], ar[l], featbuf);
        if (l == 2)
            fused_edge_kernel<true><<<node_blocks, 256>>>(bb[l]);
        else
            fused_edge_kernel<false><<<node_blocks, 256>>>(bb[l]);
        layer_in = hbuf;
    }
    score_kernel<<<score_blocks, 256>>>(src, dst, nsrc, ndst, out);
}

// round 7
// speedup vs baseline: 1.3131x; 1.3131x over previous
#include <cuda_runtime.h>
#include <cuda_fp16.h>
#include <math_constants.h>
#include <stdint.h>

#define NN 25000
#define EE 250000
#define HH 4
#define DD 64
#define HD 256   // H*D

// ---------------- scratch (device globals; no allocation allowed) -------------
__device__ __half g_feat16[NN * HD];   // x @ W for current layer, fp16
__device__ float  g_h[NN * HD];        // layer output (next layer input), fp32
__device__ __half g_hh[NN * HD];       // final layer output, fp16 (score input)
__device__ float g_elp[2 * NN * HH];
__device__ float g_erp[2 * NN * HH];
__device__ int g_cnt[NN];
__device__ int g_off[NN + 1];
__device__ int g_cur[NN];
__device__ int g_csr_src[EE];

// ---------------- helpers ----------------------------------------------------
__device__ __forceinline__ void mma_f16(float* d, const uint32_t* a, const uint32_t* b) {
    asm volatile(
        "mma.sync.aligned.m16n8k16.row.col.f32.f16.f16.f32 "
        "{%0,%1,%2,%3}, {%4,%5,%6,%7}, {%8,%9}, {%0,%1,%2,%3};"
        : "+f"(d[0]), "+f"(d[1]), "+f"(d[2]), "+f"(d[3])
        : "r"(a[0]), "r"(a[1]), "r"(a[2]), "r"(a[3]), "r"(b[0]), "r"(b[1]));
}

// ---------------- CSR build ---------------------------------------------------
__global__ __launch_bounds__(256) void csr_hist_kernel(const int* __restrict__ dst) {
    int i = blockIdx.x * blockDim.x + threadIdx.x;
    if (i < EE) atomicAdd(&g_cnt[dst[i]], 1);
}

__global__ __launch_bounds__(1024) void csr_scan_kernel() {
    __shared__ int part[1024];
    const int tid = threadIdx.x;
    const int base = tid * 25;
    int loc[25];
    int s = 0;
#pragma unroll
    for (int j = 0; j < 25; j++) {
        int idx = base + j;
        int c = (idx < NN) ? g_cnt[idx] : 0;
        loc[j] = s;
        s += c;
    }
    part[tid] = s;
    __syncthreads();
    for (int off = 1; off < 1024; off <<= 1) {
        int v = (tid >= off) ? part[tid - off] : 0;
        __syncthreads();
        part[tid] += v;
        __syncthreads();
    }
    const int excl = (tid == 0) ? 0 : part[tid - 1];
#pragma unroll
    for (int j = 0; j < 25; j++) {
        int idx = base + j;
        if (idx < NN) {
            int o = excl + loc[j];
            g_off[idx] = o;
            g_cur[idx] = o;
        }
    }
    if (tid == 0) g_off[NN] = EE;
}

__global__ __launch_bounds__(256) void csr_scatter_kernel(const int* __restrict__ src,
                                                          const int* __restrict__ dst) {
    int e = blockIdx.x * blockDim.x + threadIdx.x;
    if (e >= EE) return;
    int slot = atomicAdd(&g_cur[dst[e]], 1);
    g_csr_src[slot] = src[e];
}

// ---------------- FP16 GEMM + fused el/er + fp16 out --------------------------
// C16[M,256] = fp16(A[M,256] @ B[256,256]) via single-pass fp16 mma, fp32 accum.
// Block 128x128, BK=32, 8 warps (2m x 4n), warp 64x32 (4x4 m16n8k16 atoms).
// Layouts identical to the validated R2 bf16 kernel (minus the lo-split):
//  A smem: 128 rows x 40 halfs (stride 20 uint32);  B smem: 128 n-rows x 17
//  uint32 k-pairs. Vectorized STS.128 stores; register prefetch pipeline.
#define ASTRIDE 20   // uint32 (half-pair) per A row: 16 + 4 pad
#define BSTRIDE 17   // uint32 (k-pair) per B n-row: 16 + 1 pad

__global__ __launch_bounds__(256, 2) void gemm_fused(const float* __restrict__ A,
                                                     const float* __restrict__ B,
                                                     const float* __restrict__ alp,
                                                     const float* __restrict__ arp,
                                                     __half* __restrict__ C16) {
    __shared__ __align__(16) uint32_t As[128 * ASTRIDE];
    __shared__ __align__(16) uint32_t Bs[128 * BSTRIDE];

    const int tid = threadIdx.x;
    const int bm = blockIdx.x * 128;
    const int bn = blockIdx.y * 128;
    const int lane = tid & 31;
    const int wid = tid >> 5;
    const int wm = (wid >> 2) * 64;
    const int wn = (wid & 3) * 32;
    const int g  = lane >> 2;
    const int c  = lane & 3;
    const int c2 = c * 2;

    float acc[4][4][4];
#pragma unroll
    for (int i = 0; i < 4; i++)
#pragma unroll
        for (int j = 0; j < 4; j++)
#pragma unroll
            for (int t = 0; t < 4; t++) acc[i][j][t] = 0.f;

    // A loader: row tid>>1 (0..127), k half (tid&1)*16
    const int arow = tid >> 1;
    const int alc  = (tid & 1) * 16;
    const int agr  = bm + arow;
    const bool aval = agr < NN;
    // B loader: n = tid&127, k half (tid>>7)*16
    const int bln  = tid & 127;
    const int blk  = (tid >> 7) * 16;

    float pa[16], pb[16];

    // prefetch stage 0
    {
        if (aval) {
            const float4* s = (const float4*)(A + agr * 256 + alc);
#pragma unroll
            for (int q = 0; q < 4; q++) { float4 v = s[q]; pa[q*4+0]=v.x; pa[q*4+1]=v.y; pa[q*4+2]=v.z; pa[q*4+3]=v.w; }
        } else {
#pragma unroll
            for (int q = 0; q < 16; q++) pa[q] = 0.f;
        }
#pragma unroll
        for (int j = 0; j < 16; j++) pb[j] = B[(blk + j) * 256 + bn + bln];
    }

    for (int kk = 0; kk < 256; kk += 32) {
        // ---- store prefetched panel to shared (cvt fp32 -> half2 pairs) ----
        {
            uint32_t pk[8];
#pragma unroll
            for (int t = 0; t < 8; t++) {
                __half2 h = __floats2half2_rn(pa[2*t], pa[2*t+1]);
                pk[t] = *(uint32_t*)&h;
            }
            uint32_t* da = &As[arow * ASTRIDE + (alc >> 1)];
            *(uint4*)(da)     = make_uint4(pk[0], pk[1], pk[2], pk[3]);
            *(uint4*)(da + 4) = make_uint4(pk[4], pk[5], pk[6], pk[7]);
        }
        {
            const int base = bln * BSTRIDE + (blk >> 1);
#pragma unroll
            for (int t = 0; t < 8; t++) {
                __half2 h = __floats2half2_rn(pb[2*t], pb[2*t+1]);
                Bs[base + t] = *(uint32_t*)&h;
            }
        }
        __syncthreads();

        // ---- prefetch next stage ----
        if (kk + 32 < 256) {
            if (aval) {
                const float4* s = (const float4*)(A + agr * 256 + kk + 32 + alc);
#pragma unroll
                for (int q = 0; q < 4; q++) { float4 v = s[q]; pa[q*4+0]=v.x; pa[q*4+1]=v.y; pa[q*4+2]=v.z; pa[q*4+3]=v.w; }
            }
#pragma unroll
            for (int j = 0; j < 16; j++) pb[j] = B[(kk + 32 + blk + j) * 256 + bn + bln];
        }

        // ---- compute: 2 x k16 steps ----
#pragma unroll
        for (int ks = 0; ks < 2; ks++) {
            const int ko = ks * 8;   // uint32 (half-pair) offset in A row
            const int k2 = ks * 8;   // k-pair offset in B row
            uint32_t bfr[4][2];
#pragma unroll
            for (int j = 0; j < 4; j++) {
                const int n = wn + j * 8 + g;
                bfr[j][0] = Bs[n * BSTRIDE + k2 + c];
                bfr[j][1] = Bs[n * BSTRIDE + k2 + c + 4];
            }
#pragma unroll
            for (int i = 0; i < 4; i++) {
                const int r0 = wm + i * 16 + g;
                uint32_t afr[4];
                afr[0] = As[r0 * ASTRIDE + ko + c];
                afr[1] = As[(r0 + 8) * ASTRIDE + ko + c];
                afr[2] = As[r0 * ASTRIDE + ko + c + 4];
                afr[3] = As[(r0 + 8) * ASTRIDE + ko + c + 4];
#pragma unroll
                for (int j = 0; j < 4; j++) mma_f16(acc[i][j], afr, bfr[j]);
            }
        }
        __syncthreads();
    }

    // ---- epilogue: fp16 feat store + fused el/er partials ----
    const int colbase = bn + wn;
    const int hh_ = colbase >> 6;
    const int q_  = (colbase >> 5) & 1;
    float alv[4][2], arv[4][2];
#pragma unroll
    for (int j = 0; j < 4; j++) {
        int col = colbase + j * 8 + c2;
        alv[j][0] = alp[col];     alv[j][1] = alp[col + 1];
        arv[j][0] = arp[col];     arv[j][1] = arp[col + 1];
    }

#pragma unroll
    for (int i = 0; i < 4; i++) {
        const int r = bm + wm + i * 16 + g;
        float pel0 = 0.f, per0 = 0.f, pel1 = 0.f, per1 = 0.f;
#pragma unroll
        for (int j = 0; j < 4; j++) {
            const int col = colbase + j * 8 + c2;
            pel0 += acc[i][j][0] * alv[j][0] + acc[i][j][1] * alv[j][1];
            per0 += acc[i][j][0] * arv[j][0] + acc[i][j][1] * arv[j][1];
            pel1 += acc[i][j][2] * alv[j][0] + acc[i][j][3] * alv[j][1];
            per1 += acc[i][j][2] * arv[j][0] + acc[i][j][3] * arv[j][1];
            __half2 h01 = __floats2half2_rn(acc[i][j][0], acc[i][j][1]);
            __half2 h23 = __floats2half2_rn(acc[i][j][2], acc[i][j][3]);
            if (r < NN)     *(__half2*)(C16 + r * 256 + col)       = h01;
            if (r + 8 < NN) *(__half2*)(C16 + (r + 8) * 256 + col) = h23;
        }
#pragma unroll
        for (int o = 1; o <= 2; o <<= 1) {
            pel0 += __shfl_xor_sync(0xffffffffu, pel0, o);
            per0 += __shfl_xor_sync(0xffffffffu, per0, o);
            pel1 += __shfl_xor_sync(0xffffffffu, pel1, o);
            per1 += __shfl_xor_sync(0xffffffffu, per1, o);
        }
        if (c == 0) {
            if (r < NN) {
                g_elp[q_ * (NN * HH) + r * HH + hh_] = pel0;
                g_erp[q_ * (NN * HH) + r * HH + hh_] = per0;
            }
            if (r + 8 < NN) {
                g_elp[q_ * (NN * HH) + (r + 8) * HH + hh_] = pel1;
                g_erp[q_ * (NN * HH) + (r + 8) * HH + hh_] = per1;
            }
        }
    }
}

// ---------------- fused edge softmax + aggregation + bias/relu (single pass) --
template <bool LAST>
__global__ __launch_bounds__(256) void fused_edge_kernel(const float* __restrict__ b) {
    const int n = (blockIdx.x * blockDim.x + threadIdx.x) >> 5;
    const int lane = threadIdx.x & 31;
    if (n >= NN) return;

    const int off = g_off[n];
    const int deg = g_off[n + 1] - off;
    const int h = lane >> 3;

    const float erh = g_erp[n * HH + h] + g_erp[NN * HH + n * HH + h];

    float acc[8];
#pragma unroll
    for (int j = 0; j < 8; j++) acc[j] = 0.f;
    float ssum = 0.f;

    for (int i = 0; i < deg; i++) {
        const int s = g_csr_src[off + i];
        float e = g_elp[s * HH + h] + g_elp[NN * HH + s * HH + h] + erh;
        e = e > 0.f ? e : 0.2f * e;
        const float a = __expf(e);
        ssum += a;
        const uint4 p = *(const uint4*)(g_feat16 + s * HD + lane * 8);
        const __half2* ph = (const __half2*)&p;
        float2 f0 = __half22float2(ph[0]);
        float2 f1 = __half22float2(ph[1]);
        float2 f2 = __half22float2(ph[2]);
        float2 f3 = __half22float2(ph[3]);
        acc[0] += a * f0.x; acc[1] += a * f0.y;
        acc[2] += a * f1.x; acc[3] += a * f1.y;
        acc[4] += a * f2.x; acc[5] += a * f2.y;
        acc[6] += a * f3.x; acc[7] += a * f3.y;
    }
    const float inv = (ssum > 0.f) ? (1.f / ssum) : 0.f;

    const float4 b0 = *(const float4*)(b + lane * 8);
    const float4 b1 = *(const float4*)(b + lane * 8 + 4);
    float o0 = fmaxf(acc[0] * inv + b0.x, 0.f);
    float o1 = fmaxf(acc[1] * inv + b0.y, 0.f);
    float o2 = fmaxf(acc[2] * inv + b0.z, 0.f);
    float o3 = fmaxf(acc[3] * inv + b0.w, 0.f);
    float o4 = fmaxf(acc[4] * inv + b1.x, 0.f);
    float o5 = fmaxf(acc[5] * inv + b1.y, 0.f);
    float o6 = fmaxf(acc[6] * inv + b1.z, 0.f);
    float o7 = fmaxf(acc[7] * inv + b1.w, 0.f);

    if (LAST) {
        __half2 p0 = __floats2half2_rn(o0, o1);
        __half2 p1 = __floats2half2_rn(o2, o3);
        __half2 p2 = __floats2half2_rn(o4, o5);
        __half2 p3 = __floats2half2_rn(o6, o7);
        uint4 pk;
        pk.x = *(uint32_t*)&p0; pk.y = *(uint32_t*)&p1;
        pk.z = *(uint32_t*)&p2; pk.w = *(uint32_t*)&p3;
        ((uint4*)(g_hh + n * HD))[lane] = pk;
    } else {
        float4* o = (float4*)(g_h + n * HD + lane * 8);
        o[0] = make_float4(o0, o1, o2, o3);
        o[1] = make_float4(o4, o5, o6, o7);
    }
}

// ---------------- final dot scores (fp16 gather, fp32 accumulate) --------------
__global__ __launch_bounds__(256) void score_kernel(const int* __restrict__ src,
                                                    const int* __restrict__ dst,
                                                    const int* __restrict__ nsrc,
                                                    const int* __restrict__ ndst,
                                                    float* __restrict__ out) {
    int w = (blockIdx.x * blockDim.x + threadIdx.x) >> 5;
    int lane = threadIdx.x & 31;
    if (w >= 2 * EE) return;
    bool pos = w < EE;
    int e = pos ? w : w - EE;
    int uN = pos ? src[e] : nsrc[e];
    int vN = pos ? dst[e] : ndst[e];

    uint4 up = ((const uint4*)(g_hh + uN * HD))[lane];
    uint4 vp = ((const uint4*)(g_hh + vN * HD))[lane];
    float2 u0 = __half22float2(*(__half2*)&up.x), v0 = __half22float2(*(__half2*)&vp.x);
    float2 u1 = __half22float2(*(__half2*)&up.y), v1 = __half22float2(*(__half2*)&vp.y);
    float2 u2 = __half22float2(*(__half2*)&up.z), v2 = __half22float2(*(__half2*)&vp.z);
    float2 u3 = __half22float2(*(__half2*)&up.w), v3 = __half22float2(*(__half2*)&vp.w);
    float d = u0.x * v0.x + u0.y * v0.y + u1.x * v1.x + u1.y * v1.y +
              u2.x * v2.x + u2.y * v2.y + u3.x * v3.x + u3.y * v3.y;
#pragma unroll
    for (int off = 4; off >= 1; off >>= 1) d += __shfl_down_sync(0xffffffffu, d, off, 8);
    if ((lane & 7) == 0) {
        int h = lane >> 3;
        out[(pos ? 0 : EE * HH) + e * HH + h] = d;
    }
}

// ---------------- launch -------------------------------------------------------
extern "C" void kernel_launch(void* const* d_in, const int* in_sizes, int n_in,
                              void* d_out, int out_size) {
    const float* x    = (const float*)d_in[0];
    const int* src    = (const int*)d_in[1];
    const int* dst    = (const int*)d_in[2];
    const int* nsrc   = (const int*)d_in[3];
    const int* ndst   = (const int*)d_in[4];
    const float* W[3]  = {(const float*)d_in[5], (const float*)d_in[9],  (const float*)d_in[13]};
    const float* al[3] = {(const float*)d_in[6], (const float*)d_in[10], (const float*)d_in[14]};
    const float* ar[3] = {(const float*)d_in[7], (const float*)d_in[11], (const float*)d_in[15]};
    const float* bb[3] = {(const float*)d_in[8], (const float*)d_in[12], (const float*)d_in[16]};
    float* out = (float*)d_out;

    float* hbuf = nullptr;
    cudaGetSymbolAddress((void**)&hbuf, g_h);
    __half* featbuf = nullptr;
    cudaGetSymbolAddress((void**)&featbuf, g_feat16);
    int* cntbuf = nullptr;
    cudaGetSymbolAddress((void**)&cntbuf, g_cnt);

    // --- CSR build (dst constant across layers) ---
    cudaMemsetAsync(cntbuf, 0, NN * sizeof(int));
    csr_hist_kernel<<<(EE + 255) / 256, 256>>>(dst);
    csr_scan_kernel<<<1, 1024>>>();
    csr_scatter_kernel<<<(EE + 255) / 256, 256>>>(src, dst);

    dim3 gemm_grid((NN + 127) / 128, 2);
    const int node_blocks  = (NN * 32 + 255) / 256;
    const int score_blocks = (2 * EE * 32 + 255) / 256;

    const float* layer_in = x;
    for (int l = 0; l < 3; l++) {
        gemm_fused<<<gemm_grid, 256>>>(layer_in, W[l], al[l], ar[l], featbuf);
        if (l == 2)
            fused_edge_kernel<true><<<node_blocks, 256>>>(bb[l]);
        else
            fused_edge_kernel<false><<<node_blocks, 256>>>(bb[l]);
        layer_in = hbuf;
    }
    score_kernel<<<score_blocks, 256>>>(src, dst, nsrc, ndst, out);
}

// round 8
// speedup vs baseline: 1.4463x; 1.1015x over previous
#include <cuda_runtime.h>
#include <cuda_fp16.h>
#include <math_constants.h>
#include <stdint.h>

#define NN 25000
#define EE 250000
#define HH 4
#define DD 64
#define HD 256   // H*D

// ---------------- scratch (device globals; no allocation allowed) -------------
__device__ __align__(16) __half g_act16[NN * HD];  // layer input (fp16)
__device__ __align__(16) __half g_feat16[NN * HD]; // x @ W (fp16)
__device__ __align__(16) __half g_hh[NN * HD];     // final output (score input)
__device__ __align__(16) __half g_w16[3 * HD * HD];
__device__ float g_elp[2 * NN * HH];
__device__ float g_erp[2 * NN * HH];
__device__ int g_cnt[NN];
__device__ int g_off[NN + 1];
__device__ int g_cur[NN];
__device__ int g_csr_src[EE];

// ---------------- helpers ----------------------------------------------------
__device__ __forceinline__ void mma_f16(float* d, const uint32_t* a, const uint32_t* b) {
    asm volatile(
        "mma.sync.aligned.m16n8k16.row.col.f32.f16.f16.f32 "
        "{%0,%1,%2,%3}, {%4,%5,%6,%7}, {%8,%9}, {%0,%1,%2,%3};"
        : "+f"(d[0]), "+f"(d[1]), "+f"(d[2]), "+f"(d[3])
        : "r"(a[0]), "r"(a[1]), "r"(a[2]), "r"(a[3]), "r"(b[0]), "r"(b[1]));
}

__device__ __forceinline__ uint32_t cvta_smem(const void* p) {
    return (uint32_t)__cvta_generic_to_shared(p);
}

#define CP_ASYNC16(dst, src, sz) \
    asm volatile("cp.async.cg.shared.global [%0], [%1], 16, %2;" :: "r"(dst), "l"(src), "r"(sz))
#define CP_COMMIT() asm volatile("cp.async.commit_group;")
template <int N>
__device__ __forceinline__ void cp_wait() {
    asm volatile("cp.async.wait_group %0;" :: "n"(N));
}

// ---------------- one-time fp32 -> fp16 converts -------------------------------
__global__ __launch_bounds__(256) void cvt_x_kernel(const float* __restrict__ x) {
    int t = blockIdx.x * 256 + threadIdx.x;
    if (t >= NN * HD / 4) return;
    float4 v = ((const float4*)x)[t];
    __half2 h0 = __floats2half2_rn(v.x, v.y);
    __half2 h1 = __floats2half2_rn(v.z, v.w);
    uint2 p; p.x = *(uint32_t*)&h0; p.y = *(uint32_t*)&h1;
    ((uint2*)g_act16)[t] = p;
}

__global__ __launch_bounds__(256) void cvt_w_kernel(const float* __restrict__ W1,
                                                    const float* __restrict__ W2,
                                                    const float* __restrict__ W3) {
    int t = blockIdx.x * 256 + threadIdx.x;   // float4 index across [W1|W2|W3]
    if (t >= 3 * HD * HD / 4) return;
    const float* src = (t < 16384) ? W1 : ((t < 32768) ? W2 : W3);
    float4 v = ((const float4*)src)[t & 16383];
    __half2 h0 = __floats2half2_rn(v.x, v.y);
    __half2 h1 = __floats2half2_rn(v.z, v.w);
    uint2 p; p.x = *(uint32_t*)&h0; p.y = *(uint32_t*)&h1;
    ((uint2*)g_w16)[t] = p;
}

// ---------------- CSR build ---------------------------------------------------
__global__ __launch_bounds__(256) void csr_hist_kernel(const int* __restrict__ dst) {
    int i = blockIdx.x * blockDim.x + threadIdx.x;
    if (i < EE) atomicAdd(&g_cnt[dst[i]], 1);
}

__global__ __launch_bounds__(1024) void csr_scan_kernel() {
    __shared__ int part[1024];
    const int tid = threadIdx.x;
    const int base = tid * 25;
    int loc[25];
    int s = 0;
#pragma unroll
    for (int j = 0; j < 25; j++) {
        int idx = base + j;
        int c = (idx < NN) ? g_cnt[idx] : 0;
        loc[j] = s;
        s += c;
    }
    part[tid] = s;
    __syncthreads();
    for (int off = 1; off < 1024; off <<= 1) {
        int v = (tid >= off) ? part[tid - off] : 0;
        __syncthreads();
        part[tid] += v;
        __syncthreads();
    }
    const int excl = (tid == 0) ? 0 : part[tid - 1];
#pragma unroll
    for (int j = 0; j < 25; j++) {
        int idx = base + j;
        if (idx < NN) {
            int o = excl + loc[j];
            g_off[idx] = o;
            g_cur[idx] = o;
        }
    }
    if (tid == 0) g_off[NN] = EE;
}

__global__ __launch_bounds__(256) void csr_scatter_kernel(const int* __restrict__ src,
                                                          const int* __restrict__ dst) {
    int e = blockIdx.x * blockDim.x + threadIdx.x;
    if (e >= EE) return;
    int slot = atomicAdd(&g_cur[dst[e]], 1);
    g_csr_src[slot] = src[e];
}

// ---------------- FP16 GEMM: cp.async + ldmatrix + fused el/er ----------------
// C16[M,256] = A16[M,256] @ W16[256,256] (fp16 in, fp32 accum, fp16 out).
// Block 128x128, BK=32 (8 k-tiles), 8 warps 2m x 4n, warp 64x32.
// A smem row = 80B (64 data + 16 pad): LDSM banks 20r mod 32 all-distinct.
// B smem row = 272B (256 data + 16 pad): LDSM banks 4k mod 32 all-distinct.
// Double-buffered cp.async pipeline, one sync per k-tile.
#define BK 32
#define A_ROWB 80
#define B_ROWB 272
#define A_STAGEB (128 * A_ROWB)   // 10240
#define B_STAGEB (BK * B_ROWB)    // 8704

__global__ __launch_bounds__(256, 2) void gemm_fused(const __half* __restrict__ Ain,
                                                     const __half* __restrict__ Win,
                                                     const float* __restrict__ alp,
                                                     const float* __restrict__ arp,
                                                     __half* __restrict__ C16) {
    __shared__ __align__(16) char smem[2 * (A_STAGEB + B_STAGEB)];

    const int tid = threadIdx.x;
    const int bm = blockIdx.x * 128;
    const int bn = blockIdx.y * 128;
    const int lane = tid & 31;
    const int wid = tid >> 5;
    const int wm = (wid >> 2) * 64;
    const int wn = (wid & 3) * 32;
    const int g  = lane >> 2;
    const int c  = lane & 3;
    const int c2 = c * 2;

    const uint32_t smem_u32 = cvta_smem(smem);

    // --- cp.async producer mapping ---
    const int arow = tid >> 1, ach = (tid & 1) * 2;        // 2 chunks of 16B per thread
    const bool aval = (bm + arow) < NN;
    const uint32_t asz = aval ? 16u : 0u;
    const __half* asrc0 = Ain + (size_t)(bm + arow) * 256 + ach * 8;
    const uint32_t adst0 = smem_u32 + arow * A_ROWB + ach * 16;
    const int bkrow = tid >> 3, bch = (tid & 7) * 2;
    const __half* bsrc0 = Win + (size_t)bkrow * 256 + bn + bch * 8;
    const uint32_t bdst0 = smem_u32 + 2 * A_STAGEB + bkrow * B_ROWB + bch * 16;

    // --- ldmatrix consumer bases (per-lane) ---
    const uint32_t a_lm0 = smem_u32 + (wm + (lane & 15)) * A_ROWB + (lane >> 4) * 16;
    const uint32_t b_lm0 = smem_u32 + 2 * A_STAGEB + (lane & 15) * B_ROWB
                         + ((wn >> 3) + (lane >> 4)) * 16;

    float acc[4][4][4];
#pragma unroll
    for (int i = 0; i < 4; i++)
#pragma unroll
        for (int j = 0; j < 4; j++)
#pragma unroll
            for (int t = 0; t < 4; t++) acc[i][j][t] = 0.f;

    // issue tile 0
    CP_ASYNC16(adst0, asrc0, asz);
    CP_ASYNC16(adst0 + 16, asrc0 + 8, asz);
    CP_ASYNC16(bdst0, bsrc0, 16);
    CP_ASYNC16(bdst0 + 16, bsrc0 + 8, 16);
    CP_COMMIT();

    for (int kt = 0; kt < 8; kt++) {
        cp_wait<0>();
        __syncthreads();
        if (kt < 7) {
            const int nx = kt + 1, s = nx & 1;
            const __half* as = asrc0 + nx * BK;
            const __half* bs = bsrc0 + (size_t)nx * BK * 256;
            const uint32_t ad = adst0 + s * A_STAGEB;
            const uint32_t bd = bdst0 + s * B_STAGEB;
            CP_ASYNC16(ad, as, asz);
            CP_ASYNC16(ad + 16, as + 8, asz);
            CP_ASYNC16(bd, bs, 16);
            CP_ASYNC16(bd + 16, bs + 8, 16);
            CP_COMMIT();
        }
        const int s = kt & 1;
        const uint32_t aS = a_lm0 + s * A_STAGEB;
        const uint32_t bS = b_lm0 + s * B_STAGEB;
#pragma unroll
        for (int ks = 0; ks < 2; ks++) {
            uint32_t bfr[4][2];
#pragma unroll
            for (int jp = 0; jp < 2; jp++) {
                const uint32_t addr = bS + ks * (16 * B_ROWB) + jp * 32;
                asm volatile(
                    "ldmatrix.sync.aligned.m8n8.x4.trans.shared.b16 {%0,%1,%2,%3}, [%4];"
                    : "=r"(bfr[2*jp][0]), "=r"(bfr[2*jp][1]),
                      "=r"(bfr[2*jp+1][0]), "=r"(bfr[2*jp+1][1])
                    : "r"(addr));
            }
#pragma unroll
            for (int i = 0; i < 4; i++) {
                uint32_t afr[4];
                const uint32_t addr = aS + i * (16 * A_ROWB) + ks * 32;
                asm volatile(
                    "ldmatrix.sync.aligned.m8n8.x4.shared.b16 {%0,%1,%2,%3}, [%4];"
                    : "=r"(afr[0]), "=r"(afr[1]), "=r"(afr[2]), "=r"(afr[3])
                    : "r"(addr));
#pragma unroll
                for (int j = 0; j < 4; j++) mma_f16(acc[i][j], afr, bfr[j]);
            }
        }
    }

    // ---- epilogue: fp16 feat store + fused el/er partials ----
    const int colbase = bn + wn;
    const int hh_ = colbase >> 6;
    const int q_  = (colbase >> 5) & 1;
    float alv[4][2], arv[4][2];
#pragma unroll
    for (int j = 0; j < 4; j++) {
        int col = colbase + j * 8 + c2;
        alv[j][0] = alp[col];     alv[j][1] = alp[col + 1];
        arv[j][0] = arp[col];     arv[j][1] = arp[col + 1];
    }

#pragma unroll
    for (int i = 0; i < 4; i++) {
        const int r = bm + wm + i * 16 + g;
        float pel0 = 0.f, per0 = 0.f, pel1 = 0.f, per1 = 0.f;
#pragma unroll
        for (int j = 0; j < 4; j++) {
            const int col = colbase + j * 8 + c2;
            pel0 += acc[i][j][0] * alv[j][0] + acc[i][j][1] * alv[j][1];
            per0 += acc[i][j][0] * arv[j][0] + acc[i][j][1] * arv[j][1];
            pel1 += acc[i][j][2] * alv[j][0] + acc[i][j][3] * alv[j][1];
            per1 += acc[i][j][2] * arv[j][0] + acc[i][j][3] * arv[j][1];
            __half2 h01 = __floats2half2_rn(acc[i][j][0], acc[i][j][1]);
            __half2 h23 = __floats2half2_rn(acc[i][j][2], acc[i][j][3]);
            if (r < NN)     *(__half2*)(C16 + r * 256 + col)       = h01;
            if (r + 8 < NN) *(__half2*)(C16 + (r + 8) * 256 + col) = h23;
        }
#pragma unroll
        for (int o = 1; o <= 2; o <<= 1) {
            pel0 += __shfl_xor_sync(0xffffffffu, pel0, o);
            per0 += __shfl_xor_sync(0xffffffffu, per0, o);
            pel1 += __shfl_xor_sync(0xffffffffu, pel1, o);
            per1 += __shfl_xor_sync(0xffffffffu, per1, o);
        }
        if (c == 0) {
            if (r < NN) {
                g_elp[q_ * (NN * HH) + r * HH + hh_] = pel0;
                g_erp[q_ * (NN * HH) + r * HH + hh_] = per0;
            }
            if (r + 8 < NN) {
                g_elp[q_ * (NN * HH) + (r + 8) * HH + hh_] = pel1;
                g_erp[q_ * (NN * HH) + (r + 8) * HH + hh_] = per1;
            }
        }
    }
}

// ---------------- fused edge softmax + aggregation + bias/relu ----------------
__global__ __launch_bounds__(256) void fused_edge_kernel(const float* __restrict__ b,
                                                         __half* __restrict__ out) {
    const int n = (blockIdx.x * blockDim.x + threadIdx.x) >> 5;
    const int lane = threadIdx.x & 31;
    if (n >= NN) return;

    const int off = g_off[n];
    const int deg = g_off[n + 1] - off;
    const int h = lane >> 3;

    const float erh = g_erp[n * HH + h] + g_erp[NN * HH + n * HH + h];

    float acc[8];
#pragma unroll
    for (int j = 0; j < 8; j++) acc[j] = 0.f;
    float ssum = 0.f;

    for (int i = 0; i < deg; i++) {
        const int s = g_csr_src[off + i];
        float e = g_elp[s * HH + h] + g_elp[NN * HH + s * HH + h] + erh;
        e = e > 0.f ? e : 0.2f * e;
        const float a = __expf(e);
        ssum += a;
        const uint4 p = *(const uint4*)(g_feat16 + s * HD + lane * 8);
        const __half2* ph = (const __half2*)&p;
        float2 f0 = __half22float2(ph[0]);
        float2 f1 = __half22float2(ph[1]);
        float2 f2 = __half22float2(ph[2]);
        float2 f3 = __half22float2(ph[3]);
        acc[0] += a * f0.x; acc[1] += a * f0.y;
        acc[2] += a * f1.x; acc[3] += a * f1.y;
        acc[4] += a * f2.x; acc[5] += a * f2.y;
        acc[6] += a * f3.x; acc[7] += a * f3.y;
    }
    const float inv = (ssum > 0.f) ? (1.f / ssum) : 0.f;

    const float4 b0 = *(const float4*)(b + lane * 8);
    const float4 b1 = *(const float4*)(b + lane * 8 + 4);
    float o0 = fmaxf(acc[0] * inv + b0.x, 0.f);
    float o1 = fmaxf(acc[1] * inv + b0.y, 0.f);
    float o2 = fmaxf(acc[2] * inv + b0.z, 0.f);
    float o3 = fmaxf(acc[3] * inv + b0.w, 0.f);
    float o4 = fmaxf(acc[4] * inv + b1.x, 0.f);
    float o5 = fmaxf(acc[5] * inv + b1.y, 0.f);
    float o6 = fmaxf(acc[6] * inv + b1.z, 0.f);
    float o7 = fmaxf(acc[7] * inv + b1.w, 0.f);

    __half2 p0 = __floats2half2_rn(o0, o1);
    __half2 p1 = __floats2half2_rn(o2, o3);
    __half2 p2 = __floats2half2_rn(o4, o5);
    __half2 p3 = __floats2half2_rn(o6, o7);
    uint4 pk;
    pk.x = *(uint32_t*)&p0; pk.y = *(uint32_t*)&p1;
    pk.z = *(uint32_t*)&p2; pk.w = *(uint32_t*)&p3;
    ((uint4*)(out + n * HD))[lane] = pk;
}

// ---------------- final dot scores (fp16 gather, fp32 accumulate) --------------
__global__ __launch_bounds__(256) void score_kernel(const int* __restrict__ src,
                                                    const int* __restrict__ dst,
                                                    const int* __restrict__ nsrc,
                                                    const int* __restrict__ ndst,
                                                    float* __restrict__ out) {
    int w = (blockIdx.x * blockDim.x + threadIdx.x) >> 5;
    int lane = threadIdx.x & 31;
    if (w >= 2 * EE) return;
    bool pos = w < EE;
    int e = pos ? w : w - EE;
    int uN = pos ? src[e] : nsrc[e];
    int vN = pos ? dst[e] : ndst[e];

    uint4 up = ((const uint4*)(g_hh + uN * HD))[lane];
    uint4 vp = ((const uint4*)(g_hh + vN * HD))[lane];
    float2 u0 = __half22float2(*(__half2*)&up.x), v0 = __half22float2(*(__half2*)&vp.x);
    float2 u1 = __half22float2(*(__half2*)&up.y), v1 = __half22float2(*(__half2*)&vp.y);
    float2 u2 = __half22float2(*(__half2*)&up.z), v2 = __half22float2(*(__half2*)&vp.z);
    float2 u3 = __half22float2(*(__half2*)&up.w), v3 = __half22float2(*(__half2*)&vp.w);
    float d = u0.x * v0.x + u0.y * v0.y + u1.x * v1.x + u1.y * v1.y +
              u2.x * v2.x + u2.y * v2.y + u3.x * v3.x + u3.y * v3.y;
#pragma unroll
    for (int off = 4; off >= 1; off >>= 1) d += __shfl_down_sync(0xffffffffu, d, off, 8);
    if ((lane & 7) == 0) {
        int h = lane >> 3;
        out[(pos ? 0 : EE * HH) + e * HH + h] = d;
    }
}

// ---------------- launch -------------------------------------------------------
extern "C" void kernel_launch(void* const* d_in, const int* in_sizes, int n_in,
                              void* d_out, int out_size) {
    const float* x    = (const float*)d_in[0];
    const int* src    = (const int*)d_in[1];
    const int* dst    = (const int*)d_in[2];
    const int* nsrc   = (const int*)d_in[3];
    const int* ndst   = (const int*)d_in[4];
    const float* W[3]  = {(const float*)d_in[5], (const float*)d_in[9],  (const float*)d_in[13]};
    const float* al[3] = {(const float*)d_in[6], (const float*)d_in[10], (const float*)d_in[14]};
    const float* ar[3] = {(const float*)d_in[7], (const float*)d_in[11], (const float*)d_in[15]};
    const float* bb[3] = {(const float*)d_in[8], (const float*)d_in[12], (const float*)d_in[16]};
    float* out = (float*)d_out;

    __half* actbuf = nullptr;
    cudaGetSymbolAddress((void**)&actbuf, g_act16);
    __half* featbuf = nullptr;
    cudaGetSymbolAddress((void**)&featbuf, g_feat16);
    __half* hhbuf = nullptr;
    cudaGetSymbolAddress((void**)&hhbuf, g_hh);
    __half* wbuf = nullptr;
    cudaGetSymbolAddress((void**)&wbuf, g_w16);
    int* cntbuf = nullptr;
    cudaGetSymbolAddress((void**)&cntbuf, g_cnt);

    // --- one-time converts + CSR build ---
    cudaMemsetAsync(cntbuf, 0, NN * sizeof(int));
    cvt_x_kernel<<<(NN * HD / 4 + 255) / 256, 256>>>(x);
    cvt_w_kernel<<<(3 * HD * HD / 4 + 255) / 256, 256>>>(W[0], W[1], W[2]);
    csr_hist_kernel<<<(EE + 255) / 256, 256>>>(dst);
    csr_scan_kernel<<<1, 1024>>>();
    csr_scatter_kernel<<<(EE + 255) / 256, 256>>>(src, dst);

    dim3 gemm_grid((NN + 127) / 128, 2);
    const int node_blocks  = (NN * 32 + 255) / 256;
    const int score_blocks = (2 * EE * 32 + 255) / 256;

    for (int l = 0; l < 3; l++) {
        gemm_fused<<<gemm_grid, 256>>>(actbuf, wbuf + l * HD * HD, al[l], ar[l], featbuf);
        fused_edge_kernel<<<node_blocks, 256>>>(bb[l], (l == 2) ? hhbuf : actbuf);
    }
    score_kernel<<<score_blocks, 256>>>(src, dst, nsrc, ndst, out);
}

// round 9
// speedup vs baseline: 1.5561x; 1.0759x over previous
#include <cuda_runtime.h>
#include <cuda_fp16.h>
#include <math_constants.h>
#include <stdint.h>

#define NN 25000
#define EE 250000
#define HH 4
#define DD 64
#define HD 256   // H*D

// ---------------- scratch (device globals; no allocation allowed) -------------
__device__ __align__(16) __half g_act16[NN * HD];  // layer input (fp16)
__device__ __align__(16) __half g_feat16[NN * HD]; // x @ W (fp16)
__device__ __align__(16) __half g_hh[NN * HD];     // final output (score input)
__device__ __align__(16) __half g_w16[3 * HD * HD];
__device__ float g_elp[2 * NN * HH];
__device__ float g_erp[2 * NN * HH];
__device__ int g_cnt[NN];
__device__ int g_off[NN + 1];
__device__ int g_cur[NN];
__device__ int g_csr_src[EE];

// ---------------- helpers ----------------------------------------------------
__device__ __forceinline__ void mma_f16(float* d, const uint32_t* a, const uint32_t* b) {
    asm volatile(
        "mma.sync.aligned.m16n8k16.row.col.f32.f16.f16.f32 "
        "{%0,%1,%2,%3}, {%4,%5,%6,%7}, {%8,%9}, {%0,%1,%2,%3};"
        : "+f"(d[0]), "+f"(d[1]), "+f"(d[2]), "+f"(d[3])
        : "r"(a[0]), "r"(a[1]), "r"(a[2]), "r"(a[3]), "r"(b[0]), "r"(b[1]));
}

__device__ __forceinline__ uint32_t cvta_smem(const void* p) {
    return (uint32_t)__cvta_generic_to_shared(p);
}

#define CP_ASYNC16(dst, src, sz) \
    asm volatile("cp.async.cg.shared.global [%0], [%1], 16, %2;" :: "r"(dst), "l"(src), "r"(sz))
#define CP_COMMIT() asm volatile("cp.async.commit_group;")
template <int N>
__device__ __forceinline__ void cp_wait() {
    asm volatile("cp.async.wait_group %0;" :: "n"(N));
}

// ---------------- one-time fp32 -> fp16 converts -------------------------------
__global__ __launch_bounds__(256) void cvt_x_kernel(const float* __restrict__ x) {
    int t = blockIdx.x * 256 + threadIdx.x;
    if (t >= NN * HD / 4) return;
    float4 v = ((const float4*)x)[t];
    __half2 h0 = __floats2half2_rn(v.x, v.y);
    __half2 h1 = __floats2half2_rn(v.z, v.w);
    uint2 p; p.x = *(uint32_t*)&h0; p.y = *(uint32_t*)&h1;
    ((uint2*)g_act16)[t] = p;
}

__global__ __launch_bounds__(256) void cvt_w_kernel(const float* __restrict__ W1,
                                                    const float* __restrict__ W2,
                                                    const float* __restrict__ W3) {
    int t = blockIdx.x * 256 + threadIdx.x;
    if (t >= 3 * HD * HD / 4) return;
    const float* src = (t < 16384) ? W1 : ((t < 32768) ? W2 : W3);
    float4 v = ((const float4*)src)[t & 16383];
    __half2 h0 = __floats2half2_rn(v.x, v.y);
    __half2 h1 = __floats2half2_rn(v.z, v.w);
    uint2 p; p.x = *(uint32_t*)&h0; p.y = *(uint32_t*)&h1;
    ((uint2*)g_w16)[t] = p;
}

// ---------------- CSR build ---------------------------------------------------
__global__ __launch_bounds__(256) void csr_hist_kernel(const int* __restrict__ dst) {
    int i = blockIdx.x * blockDim.x + threadIdx.x;
    if (i < EE) atomicAdd(&g_cnt[dst[i]], 1);
}

// single block, 1024 threads, coalesced smem staging.
// dynamic smem: sm[0..NN) counts -> exclusive prefix (in place); part[] after.
__global__ __launch_bounds__(1024) void csr_scan_kernel() {
    extern __shared__ int sm[];
    int* part = sm + NN;
    const int tid = threadIdx.x;

    // phase 1: coalesced load counts into smem
    for (int i = tid; i < NN; i += 1024) sm[i] = g_cnt[i];
    __syncthreads();

    // phase 2: per-thread serial sum over 25 elements (stride-25 banks: conflict-free)
    const int base = tid * 25;
    int s = 0;
#pragma unroll
    for (int j = 0; j < 25; j++) {
        int idx = base + j;
        if (idx < NN) s += sm[idx];
    }
    part[tid] = s;
    __syncthreads();

    // phase 3: Hillis-Steele scan over 1024 partials
    for (int off = 1; off < 1024; off <<= 1) {
        int v = (tid >= off) ? part[tid - off] : 0;
        __syncthreads();
        part[tid] += v;
        __syncthreads();
    }
    int run = (tid == 0) ? 0 : part[tid - 1];

    // phase 4: in-place exclusive prefix within the 25-element chunk
#pragma unroll
    for (int j = 0; j < 25; j++) {
        int idx = base + j;
        if (idx < NN) {
            int c = sm[idx];
            sm[idx] = run;
            run += c;
        }
    }
    __syncthreads();

    // phase 5: coalesced store to g_off and g_cur
    for (int i = tid; i < NN; i += 1024) {
        int o = sm[i];
        g_off[i] = o;
        g_cur[i] = o;
    }
    if (tid == 0) g_off[NN] = EE;
}

__global__ __launch_bounds__(256) void csr_scatter_kernel(const int* __restrict__ src,
                                                          const int* __restrict__ dst) {
    int e = blockIdx.x * blockDim.x + threadIdx.x;
    if (e >= EE) return;
    int slot = atomicAdd(&g_cur[dst[e]], 1);
    g_csr_src[slot] = src[e];
}

// ---------------- FP16 GEMM: cp.async + ldmatrix + fused el/er ----------------
#define BK 32
#define A_ROWB 80
#define B_ROWB 272
#define A_STAGEB (128 * A_ROWB)   // 10240
#define B_STAGEB (BK * B_ROWB)    // 8704

__global__ __launch_bounds__(256, 2) void gemm_fused(const __half* __restrict__ Ain,
                                                     const __half* __restrict__ Win,
                                                     const float* __restrict__ alp,
                                                     const float* __restrict__ arp,
                                                     __half* __restrict__ C16) {
    __shared__ __align__(16) char smem[2 * (A_STAGEB + B_STAGEB)];

    const int tid = threadIdx.x;
    const int bm = blockIdx.x * 128;
    const int bn = blockIdx.y * 128;
    const int lane = tid & 31;
    const int wid = tid >> 5;
    const int wm = (wid >> 2) * 64;
    const int wn = (wid & 3) * 32;
    const int g  = lane >> 2;
    const int c  = lane & 3;
    const int c2 = c * 2;

    const uint32_t smem_u32 = cvta_smem(smem);

    const int arow = tid >> 1, ach = (tid & 1) * 2;
    const bool aval = (bm + arow) < NN;
    const uint32_t asz = aval ? 16u : 0u;
    const __half* asrc0 = Ain + (size_t)(bm + arow) * 256 + ach * 8;
    const uint32_t adst0 = smem_u32 + arow * A_ROWB + ach * 16;
    const int bkrow = tid >> 3, bch = (tid & 7) * 2;
    const __half* bsrc0 = Win + (size_t)bkrow * 256 + bn + bch * 8;
    const uint32_t bdst0 = smem_u32 + 2 * A_STAGEB + bkrow * B_ROWB + bch * 16;

    const uint32_t a_lm0 = smem_u32 + (wm + (lane & 15)) * A_ROWB + (lane >> 4) * 16;
    const uint32_t b_lm0 = smem_u32 + 2 * A_STAGEB + (lane & 15) * B_ROWB
                         + ((wn >> 3) + (lane >> 4)) * 16;

    float acc[4][4][4];
#pragma unroll
    for (int i = 0; i < 4; i++)
#pragma unroll
        for (int j = 0; j < 4; j++)
#pragma unroll
            for (int t = 0; t < 4; t++) acc[i][j][t] = 0.f;

    CP_ASYNC16(adst0, asrc0, asz);
    CP_ASYNC16(adst0 + 16, asrc0 + 8, asz);
    CP_ASYNC16(bdst0, bsrc0, 16);
    CP_ASYNC16(bdst0 + 16, bsrc0 + 8, 16);
    CP_COMMIT();

    for (int kt = 0; kt < 8; kt++) {
        cp_wait<0>();
        __syncthreads();
        if (kt < 7) {
            const int nx = kt + 1, s = nx & 1;
            const __half* as = asrc0 + nx * BK;
            const __half* bs = bsrc0 + (size_t)nx * BK * 256;
            const uint32_t ad = adst0 + s * A_STAGEB;
            const uint32_t bd = bdst0 + s * B_STAGEB;
            CP_ASYNC16(ad, as, asz);
            CP_ASYNC16(ad + 16, as + 8, asz);
            CP_ASYNC16(bd, bs, 16);
            CP_ASYNC16(bd + 16, bs + 8, 16);
            CP_COMMIT();
        }
        const int s = kt & 1;
        const uint32_t aS = a_lm0 + s * A_STAGEB;
        const uint32_t bS = b_lm0 + s * B_STAGEB;
#pragma unroll
        for (int ks = 0; ks < 2; ks++) {
            uint32_t bfr[4][2];
#pragma unroll
            for (int jp = 0; jp < 2; jp++) {
                const uint32_t addr = bS + ks * (16 * B_ROWB) + jp * 32;
                asm volatile(
                    "ldmatrix.sync.aligned.m8n8.x4.trans.shared.b16 {%0,%1,%2,%3}, [%4];"
                    : "=r"(bfr[2*jp][0]), "=r"(bfr[2*jp][1]),
                      "=r"(bfr[2*jp+1][0]), "=r"(bfr[2*jp+1][1])
                    : "r"(addr));
            }
#pragma unroll
            for (int i = 0; i < 4; i++) {
                uint32_t afr[4];
                const uint32_t addr = aS + i * (16 * A_ROWB) + ks * 32;
                asm volatile(
                    "ldmatrix.sync.aligned.m8n8.x4.shared.b16 {%0,%1,%2,%3}, [%4];"
                    : "=r"(afr[0]), "=r"(afr[1]), "=r"(afr[2]), "=r"(afr[3])
                    : "r"(addr));
#pragma unroll
                for (int j = 0; j < 4; j++) mma_f16(acc[i][j], afr, bfr[j]);
            }
        }
    }

    // ---- epilogue: fp16 feat store + fused el/er partials ----
    const int colbase = bn + wn;
    const int hh_ = colbase >> 6;
    const int q_  = (colbase >> 5) & 1;
    float alv[4][2], arv[4][2];
#pragma unroll
    for (int j = 0; j < 4; j++) {
        int col = colbase + j * 8 + c2;
        alv[j][0] = alp[col];     alv[j][1] = alp[col + 1];
        arv[j][0] = arp[col];     arv[j][1] = arp[col + 1];
    }

#pragma unroll
    for (int i = 0; i < 4; i++) {
        const int r = bm + wm + i * 16 + g;
        float pel0 = 0.f, per0 = 0.f, pel1 = 0.f, per1 = 0.f;
#pragma unroll
        for (int j = 0; j < 4; j++) {
            const int col = colbase + j * 8 + c2;
            pel0 += acc[i][j][0] * alv[j][0] + acc[i][j][1] * alv[j][1];
            per0 += acc[i][j][0] * arv[j][0] + acc[i][j][1] * arv[j][1];
            pel1 += acc[i][j][2] * alv[j][0] + acc[i][j][3] * alv[j][1];
            per1 += acc[i][j][2] * arv[j][0] + acc[i][j][3] * arv[j][1];
            __half2 h01 = __floats2half2_rn(acc[i][j][0], acc[i][j][1]);
            __half2 h23 = __floats2half2_rn(acc[i][j][2], acc[i][j][3]);
            if (r < NN)     *(__half2*)(C16 + r * 256 + col)       = h01;
            if (r + 8 < NN) *(__half2*)(C16 + (r + 8) * 256 + col) = h23;
        }
#pragma unroll
        for (int o = 1; o <= 2; o <<= 1) {
            pel0 += __shfl_xor_sync(0xffffffffu, pel0, o);
            per0 += __shfl_xor_sync(0xffffffffu, per0, o);
            pel1 += __shfl_xor_sync(0xffffffffu, pel1, o);
            per1 += __shfl_xor_sync(0xffffffffu, per1, o);
        }
        if (c == 0) {
            if (r < NN) {
                g_elp[q_ * (NN * HH) + r * HH + hh_] = pel0;
                g_erp[q_ * (NN * HH) + r * HH + hh_] = per0;
            }
            if (r + 8 < NN) {
                g_elp[q_ * (NN * HH) + (r + 8) * HH + hh_] = pel1;
                g_erp[q_ * (NN * HH) + (r + 8) * HH + hh_] = per1;
            }
        }
    }
}

// ---------------- fused edge softmax + aggregation + bias/relu ----------------
// Warp per node. Edge indices loaded 32-wide coalesced + shfl broadcast, so
// gathers for up to 32 edges issue without waiting on dependent index loads.
__global__ __launch_bounds__(256) void fused_edge_kernel(const float* __restrict__ b,
                                                         __half* __restrict__ out) {
    const int n = (blockIdx.x * blockDim.x + threadIdx.x) >> 5;
    const int lane = threadIdx.x & 31;
    if (n >= NN) return;

    const int off = g_off[n];
    const int deg = g_off[n + 1] - off;
    const int h = lane >> 3;

    const float erh = g_erp[n * HH + h] + g_erp[NN * HH + n * HH + h];

    float acc[8];
#pragma unroll
    for (int j = 0; j < 8; j++) acc[j] = 0.f;
    float ssum = 0.f;

    for (int base = 0; base < deg; base += 32) {
        const int myi = base + lane;
        const int sv = (myi < deg) ? g_csr_src[off + myi] : 0;
        const int cnt = min(32, deg - base);
#pragma unroll 4
        for (int j = 0; j < cnt; j++) {
            const int s = __shfl_sync(0xffffffffu, sv, j);
            float e = g_elp[s * HH + h] + g_elp[NN * HH + s * HH + h] + erh;
            e = e > 0.f ? e : 0.2f * e;
            const float a = __expf(e);
            ssum += a;
            const uint4 p = *(const uint4*)(g_feat16 + s * HD + lane * 8);
            const __half2* ph = (const __half2*)&p;
            float2 f0 = __half22float2(ph[0]);
            float2 f1 = __half22float2(ph[1]);
            float2 f2 = __half22float2(ph[2]);
            float2 f3 = __half22float2(ph[3]);
            acc[0] += a * f0.x; acc[1] += a * f0.y;
            acc[2] += a * f1.x; acc[3] += a * f1.y;
            acc[4] += a * f2.x; acc[5] += a * f2.y;
            acc[6] += a * f3.x; acc[7] += a * f3.y;
        }
    }
    const float inv = (ssum > 0.f) ? (1.f / ssum) : 0.f;

    const float4 b0 = *(const float4*)(b + lane * 8);
    const float4 b1 = *(const float4*)(b + lane * 8 + 4);
    float o0 = fmaxf(acc[0] * inv + b0.x, 0.f);
    float o1 = fmaxf(acc[1] * inv + b0.y, 0.f);
    float o2 = fmaxf(acc[2] * inv + b0.z, 0.f);
    float o3 = fmaxf(acc[3] * inv + b0.w, 0.f);
    float o4 = fmaxf(acc[4] * inv + b1.x, 0.f);
    float o5 = fmaxf(acc[5] * inv + b1.y, 0.f);
    float o6 = fmaxf(acc[6] * inv + b1.z, 0.f);
    float o7 = fmaxf(acc[7] * inv + b1.w, 0.f);

    __half2 p0 = __floats2half2_rn(o0, o1);
    __half2 p1 = __floats2half2_rn(o2, o3);
    __half2 p2 = __floats2half2_rn(o4, o5);
    __half2 p3 = __floats2half2_rn(o6, o7);
    uint4 pk;
    pk.x = *(uint32_t*)&p0; pk.y = *(uint32_t*)&p1;
    pk.z = *(uint32_t*)&p2; pk.w = *(uint32_t*)&p3;
    ((uint4*)(out + n * HD))[lane] = pk;
}

// ---------------- final dot scores (fp16 gather, fp32 accumulate) --------------
__global__ __launch_bounds__(256) void score_kernel(const int* __restrict__ src,
                                                    const int* __restrict__ dst,
                                                    const int* __restrict__ nsrc,
                                                    const int* __restrict__ ndst,
                                                    float* __restrict__ out) {
    int w = (blockIdx.x * blockDim.x + threadIdx.x) >> 5;
    int lane = threadIdx.x & 31;
    if (w >= 2 * EE) return;
    bool pos = w < EE;
    int e = pos ? w : w - EE;
    int uN = pos ? src[e] : nsrc[e];
    int vN = pos ? dst[e] : ndst[e];

    uint4 up = ((const uint4*)(g_hh + uN * HD))[lane];
    uint4 vp = ((const uint4*)(g_hh + vN * HD))[lane];
    float2 u0 = __half22float2(*(__half2*)&up.x), v0 = __half22float2(*(__half2*)&vp.x);
    float2 u1 = __half22float2(*(__half2*)&up.y), v1 = __half22float2(*(__half2*)&vp.y);
    float2 u2 = __half22float2(*(__half2*)&up.z), v2 = __half22float2(*(__half2*)&vp.z);
    float2 u3 = __half22float2(*(__half2*)&up.w), v3 = __half22float2(*(__half2*)&vp.w);
    float d = u0.x * v0.x + u0.y * v0.y + u1.x * v1.x + u1.y * v1.y +
              u2.x * v2.x + u2.y * v2.y + u3.x * v3.x + u3.y * v3.y;
#pragma unroll
    for (int off = 4; off >= 1; off >>= 1) d += __shfl_down_sync(0xffffffffu, d, off, 8);
    if ((lane & 7) == 0) {
        int h = lane >> 3;
        out[(pos ? 0 : EE * HH) + e * HH + h] = d;
    }
}

// ---------------- launch -------------------------------------------------------
extern "C" void kernel_launch(void* const* d_in, const int* in_sizes, int n_in,
                              void* d_out, int out_size) {
    const float* x    = (const float*)d_in[0];
    const int* src    = (const int*)d_in[1];
    const int* dst    = (const int*)d_in[2];
    const int* nsrc   = (const int*)d_in[3];
    const int* ndst   = (const int*)d_in[4];
    const float* W[3]  = {(const float*)d_in[5], (const float*)d_in[9],  (const float*)d_in[13]};
    const float* al[3] = {(const float*)d_in[6], (const float*)d_in[10], (const float*)d_in[14]};
    const float* ar[3] = {(const float*)d_in[7], (const float*)d_in[11], (const float*)d_in[15]};
    const float* bb[3] = {(const float*)d_in[8], (const float*)d_in[12], (const float*)d_in[16]};
    float* out = (float*)d_out;

    __half* actbuf = nullptr;
    cudaGetSymbolAddress((void**)&actbuf, g_act16);
    __half* featbuf = nullptr;
    cudaGetSymbolAddress((void**)&featbuf, g_feat16);
    __half* hhbuf = nullptr;
    cudaGetSymbolAddress((void**)&hhbuf, g_hh);
    __half* wbuf = nullptr;
    cudaGetSymbolAddress((void**)&wbuf, g_w16);
    int* cntbuf = nullptr;
    cudaGetSymbolAddress((void**)&cntbuf, g_cnt);

    // --- one-time converts + CSR build ---
    cudaMemsetAsync(cntbuf, 0, NN * sizeof(int));
    cvt_x_kernel<<<(NN * HD / 4 + 255) / 256, 256>>>(x);
    cvt_w_kernel<<<(3 * HD * HD / 4 + 255) / 256, 256>>>(W[0], W[1], W[2]);
    csr_hist_kernel<<<(EE + 255) / 256, 256>>>(dst);

    const int scan_smem = (NN + 1024) * (int)sizeof(int);
    cudaFuncSetAttribute(csr_scan_kernel, cudaFuncAttributeMaxDynamicSharedMemorySize, scan_smem);
    csr_scan_kernel<<<1, 1024, scan_smem>>>();
    csr_scatter_kernel<<<(EE + 255) / 256, 256>>>(src, dst);

    dim3 gemm_grid((NN + 127) / 128, 2);
    const int node_blocks  = (NN * 32 + 255) / 256;
    const int score_blocks = (2 * EE * 32 + 255) / 256;

    for (int l = 0; l < 3; l++) {
        gemm_fused<<<gemm_grid, 256>>>(actbuf, wbuf + l * HD * HD, al[l], ar[l], featbuf);
        fused_edge_kernel<<<node_blocks, 256>>>(bb[l], (l == 2) ? hhbuf : actbuf);
    }
    score_kernel<<<score_blocks, 256>>>(src, dst, nsrc, ndst, out);
}

// round 10
// speedup vs baseline: 1.6519x; 1.0616x over previous
#include <cuda_runtime.h>
#include <cuda_fp16.h>
#include <math_constants.h>
#include <stdint.h>

#define NN 25000
#define EE 250000
#define HH 4
#define DD 64
#define HD 256   // H*D

// ---------------- scratch (device globals; no allocation allowed) -------------
__device__ __align__(16) __half g_act16[NN * HD];  // layer input (fp16)
__device__ __align__(16) __half g_feat16[NN * HD]; // x @ W (fp16)
__device__ __align__(16) __half g_hh[NN * HD];     // final output (score input)
__device__ __align__(16) __half g_w16[3 * HD * HD];
__device__ float g_elp[2 * NN * HH];
__device__ float g_erp[2 * NN * HH];
__device__ int g_cnt[NN];
__device__ int g_off[NN + 1];
__device__ int g_cur[NN];
__device__ int g_csr_src[EE];

// ---------------- helpers ----------------------------------------------------
__device__ __forceinline__ void mma_f16(float* d, const uint32_t* a, const uint32_t* b) {
    asm volatile(
        "mma.sync.aligned.m16n8k16.row.col.f32.f16.f16.f32 "
        "{%0,%1,%2,%3}, {%4,%5,%6,%7}, {%8,%9}, {%0,%1,%2,%3};"
        : "+f"(d[0]), "+f"(d[1]), "+f"(d[2]), "+f"(d[3])
        : "r"(a[0]), "r"(a[1]), "r"(a[2]), "r"(a[3]), "r"(b[0]), "r"(b[1]));
}

__device__ __forceinline__ uint32_t cvta_smem(const void* p) {
    return (uint32_t)__cvta_generic_to_shared(p);
}

#define CP_ASYNC16(dst, src, sz) \
    asm volatile("cp.async.cg.shared.global [%0], [%1], 16, %2;" :: "r"(dst), "l"(src), "r"(sz))
#define CP_COMMIT() asm volatile("cp.async.commit_group;")
template <int N>
__device__ __forceinline__ void cp_wait() {
    asm volatile("cp.async.wait_group %0;" :: "n"(N));
}

// ---------------- one-time fp32 -> fp16 converts (x and all W, one kernel) ----
#define NX4 (NN * HD / 4)          // 1,600,000 float4 of x
#define NW4 (3 * HD * HD / 4)      // 49,152 float4 of W
__global__ __launch_bounds__(256) void cvt_all_kernel(const float* __restrict__ x,
                                                      const float* __restrict__ W1,
                                                      const float* __restrict__ W2,
                                                      const float* __restrict__ W3) {
    int t = blockIdx.x * 256 + threadIdx.x;
    float4 v;
    uint2* dst;
    if (t < NX4) {
        v = ((const float4*)x)[t];
        dst = ((uint2*)g_act16) + t;
    } else {
        int u = t - NX4;
        if (u >= NW4) return;
        const float* src = (u < 16384) ? W1 : ((u < 32768) ? W2 : W3);
        v = ((const float4*)src)[u & 16383];
        dst = ((uint2*)g_w16) + u;
    }
    __half2 h0 = __floats2half2_rn(v.x, v.y);
    __half2 h1 = __floats2half2_rn(v.z, v.w);
    uint2 p; p.x = *(uint32_t*)&h0; p.y = *(uint32_t*)&h1;
    *dst = p;
}

// ---------------- CSR build ---------------------------------------------------
__global__ __launch_bounds__(256) void csr_hist_kernel(const int* __restrict__ dst) {
    int i = blockIdx.x * blockDim.x + threadIdx.x;
    if (i < EE) atomicAdd(&g_cnt[dst[i]], 1);
}

// single block, 1024 threads, coalesced smem staging, shfl-based scan (3 bars).
__global__ __launch_bounds__(1024) void csr_scan_kernel() {
    extern __shared__ int sm[];   // NN ints
    __shared__ int wsum[32];
    const int tid = threadIdx.x;
    const int lane = tid & 31, w = tid >> 5;

    // coalesced load counts
    for (int i = tid; i < NN; i += 1024) sm[i] = g_cnt[i];
    __syncthreads();

    // per-thread serial sum over 25 elements
    const int base = tid * 25;
    int s = 0;
#pragma unroll
    for (int j = 0; j < 25; j++) {
        int idx = base + j;
        if (idx < NN) s += sm[idx];
    }
    // warp inclusive scan (shfl, no barriers)
    int incl = s;
#pragma unroll
    for (int o = 1; o < 32; o <<= 1) {
        int v = __shfl_up_sync(0xffffffffu, incl, o);
        if (lane >= o) incl += v;
    }
    if (lane == 31) wsum[w] = incl;
    __syncthreads();
    if (w == 0) {
        int t = wsum[lane];
        int ti = t;
#pragma unroll
        for (int o = 1; o < 32; o <<= 1) {
            int v = __shfl_up_sync(0xffffffffu, ti, o);
            if (lane >= o) ti += v;
        }
        wsum[lane] = ti - t;   // exclusive warp offset
    }
    __syncthreads();
    int run = wsum[w] + (incl - s);   // exclusive prefix for this thread's chunk

    // in-place exclusive prefix within chunk
#pragma unroll
    for (int j = 0; j < 25; j++) {
        int idx = base + j;
        if (idx < NN) {
            int c = sm[idx];
            sm[idx] = run;
            run += c;
        }
    }
    __syncthreads();

    // coalesced store
    for (int i = tid; i < NN; i += 1024) {
        int o = sm[i];
        g_off[i] = o;
        g_cur[i] = o;
    }
    if (tid == 0) g_off[NN] = EE;
}

__global__ __launch_bounds__(256) void csr_scatter_kernel(const int* __restrict__ src,
                                                          const int* __restrict__ dst) {
    int e = blockIdx.x * blockDim.x + threadIdx.x;
    if (e >= EE) return;
    int slot = atomicAdd(&g_cur[dst[e]], 1);
    g_csr_src[slot] = src[e];
}

// ---------------- FP16 GEMM: cp.async + ldmatrix + fused el/er ----------------
#define BK 32
#define A_ROWB 80
#define B_ROWB 272
#define A_STAGEB (128 * A_ROWB)   // 10240
#define B_STAGEB (BK * B_ROWB)    // 8704

__global__ __launch_bounds__(256, 2) void gemm_fused(const __half* __restrict__ Ain,
                                                     const __half* __restrict__ Win,
                                                     const float* __restrict__ alp,
                                                     const float* __restrict__ arp,
                                                     __half* __restrict__ C16) {
    __shared__ __align__(16) char smem[2 * (A_STAGEB + B_STAGEB)];

    const int tid = threadIdx.x;
    const int bm = blockIdx.x * 128;
    const int bn = blockIdx.y * 128;
    const int lane = tid & 31;
    const int wid = tid >> 5;
    const int wm = (wid >> 2) * 64;
    const int wn = (wid & 3) * 32;
    const int g  = lane >> 2;
    const int c  = lane & 3;
    const int c2 = c * 2;

    const uint32_t smem_u32 = cvta_smem(smem);

    const int arow = tid >> 1, ach = (tid & 1) * 2;
    const bool aval = (bm + arow) < NN;
    const uint32_t asz = aval ? 16u : 0u;
    const __half* asrc0 = Ain + (size_t)(bm + arow) * 256 + ach * 8;
    const uint32_t adst0 = smem_u32 + arow * A_ROWB + ach * 16;
    const int bkrow = tid >> 3, bch = (tid & 7) * 2;
    const __half* bsrc0 = Win + (size_t)bkrow * 256 + bn + bch * 8;
    const uint32_t bdst0 = smem_u32 + 2 * A_STAGEB + bkrow * B_ROWB + bch * 16;

    const uint32_t a_lm0 = smem_u32 + (wm + (lane & 15)) * A_ROWB + (lane >> 4) * 16;
    const uint32_t b_lm0 = smem_u32 + 2 * A_STAGEB + (lane & 15) * B_ROWB
                         + ((wn >> 3) + (lane >> 4)) * 16;

    float acc[4][4][4];
#pragma unroll
    for (int i = 0; i < 4; i++)
#pragma unroll
        for (int j = 0; j < 4; j++)
#pragma unroll
            for (int t = 0; t < 4; t++) acc[i][j][t] = 0.f;

    CP_ASYNC16(adst0, asrc0, asz);
    CP_ASYNC16(adst0 + 16, asrc0 + 8, asz);
    CP_ASYNC16(bdst0, bsrc0, 16);
    CP_ASYNC16(bdst0 + 16, bsrc0 + 8, 16);
    CP_COMMIT();

    for (int kt = 0; kt < 8; kt++) {
        cp_wait<0>();
        __syncthreads();
        if (kt < 7) {
            const int nx = kt + 1, s = nx & 1;
            const __half* as = asrc0 + nx * BK;
            const __half* bs = bsrc0 + (size_t)nx * BK * 256;
            const uint32_t ad = adst0 + s * A_STAGEB;
            const uint32_t bd = bdst0 + s * B_STAGEB;
            CP_ASYNC16(ad, as, asz);
            CP_ASYNC16(ad + 16, as + 8, asz);
            CP_ASYNC16(bd, bs, 16);
            CP_ASYNC16(bd + 16, bs + 8, 16);
            CP_COMMIT();
        }
        const int s = kt & 1;
        const uint32_t aS = a_lm0 + s * A_STAGEB;
        const uint32_t bS = b_lm0 + s * B_STAGEB;
#pragma unroll
        for (int ks = 0; ks < 2; ks++) {
            uint32_t bfr[4][2];
#pragma unroll
            for (int jp = 0; jp < 2; jp++) {
                const uint32_t addr = bS + ks * (16 * B_ROWB) + jp * 32;
                asm volatile(
                    "ldmatrix.sync.aligned.m8n8.x4.trans.shared.b16 {%0,%1,%2,%3}, [%4];"
                    : "=r"(bfr[2*jp][0]), "=r"(bfr[2*jp][1]),
                      "=r"(bfr[2*jp+1][0]), "=r"(bfr[2*jp+1][1])
                    : "r"(addr));
            }
#pragma unroll
            for (int i = 0; i < 4; i++) {
                uint32_t afr[4];
                const uint32_t addr = aS + i * (16 * A_ROWB) + ks * 32;
                asm volatile(
                    "ldmatrix.sync.aligned.m8n8.x4.shared.b16 {%0,%1,%2,%3}, [%4];"
                    : "=r"(afr[0]), "=r"(afr[1]), "=r"(afr[2]), "=r"(afr[3])
                    : "r"(addr));
#pragma unroll
                for (int j = 0; j < 4; j++) mma_f16(acc[i][j], afr, bfr[j]);
            }
        }
    }

    // ---- epilogue: fp16 feat store + fused el/er partials ----
    const int colbase = bn + wn;
    const int hh_ = colbase >> 6;
    const int q_  = (colbase >> 5) & 1;
    float alv[4][2], arv[4][2];
#pragma unroll
    for (int j = 0; j < 4; j++) {
        int col = colbase + j * 8 + c2;
        alv[j][0] = alp[col];     alv[j][1] = alp[col + 1];
        arv[j][0] = arp[col];     arv[j][1] = arp[col + 1];
    }

#pragma unroll
    for (int i = 0; i < 4; i++) {
        const int r = bm + wm + i * 16 + g;
        float pel0 = 0.f, per0 = 0.f, pel1 = 0.f, per1 = 0.f;
#pragma unroll
        for (int j = 0; j < 4; j++) {
            const int col = colbase + j * 8 + c2;
            pel0 += acc[i][j][0] * alv[j][0] + acc[i][j][1] * alv[j][1];
            per0 += acc[i][j][0] * arv[j][0] + acc[i][j][1] * arv[j][1];
            pel1 += acc[i][j][2] * alv[j][0] + acc[i][j][3] * alv[j][1];
            per1 += acc[i][j][2] * arv[j][0] + acc[i][j][3] * arv[j][1];
            __half2 h01 = __floats2half2_rn(acc[i][j][0], acc[i][j][1]);
            __half2 h23 = __floats2half2_rn(acc[i][j][2], acc[i][j][3]);
            if (r < NN)     *(__half2*)(C16 + r * 256 + col)       = h01;
            if (r + 8 < NN) *(__half2*)(C16 + (r + 8) * 256 + col) = h23;
        }
#pragma unroll
        for (int o = 1; o <= 2; o <<= 1) {
            pel0 += __shfl_xor_sync(0xffffffffu, pel0, o);
            per0 += __shfl_xor_sync(0xffffffffu, per0, o);
            pel1 += __shfl_xor_sync(0xffffffffu, pel1, o);
            per1 += __shfl_xor_sync(0xffffffffu, per1, o);
        }
        if (c == 0) {
            if (r < NN) {
                g_elp[q_ * (NN * HH) + r * HH + hh_] = pel0;
                g_erp[q_ * (NN * HH) + r * HH + hh_] = per0;
            }
            if (r + 8 < NN) {
                g_elp[q_ * (NN * HH) + (r + 8) * HH + hh_] = pel1;
                g_erp[q_ * (NN * HH) + (r + 8) * HH + hh_] = per1;
            }
        }
    }
}

// ---------------- fused edge softmax + aggregation + bias/relu ----------------
__global__ __launch_bounds__(256) void fused_edge_kernel(const float* __restrict__ b,
                                                         __half* __restrict__ out) {
    const int n = (blockIdx.x * blockDim.x + threadIdx.x) >> 5;
    const int lane = threadIdx.x & 31;
    if (n >= NN) return;

    const int off = g_off[n];
    const int deg = g_off[n + 1] - off;
    const int h = lane >> 3;

    const float erh = g_erp[n * HH + h] + g_erp[NN * HH + n * HH + h];

    float acc[8];
#pragma unroll
    for (int j = 0; j < 8; j++) acc[j] = 0.f;
    float ssum = 0.f;

    for (int base = 0; base < deg; base += 32) {
        const int myi = base + lane;
        const int sv = (myi < deg) ? g_csr_src[off + myi] : 0;
        const int cnt = min(32, deg - base);
#pragma unroll 4
        for (int j = 0; j < cnt; j++) {
            const int s = __shfl_sync(0xffffffffu, sv, j);
            float e = g_elp[s * HH + h] + g_elp[NN * HH + s * HH + h] + erh;
            e = e > 0.f ? e : 0.2f * e;
            const float a = __expf(e);
            ssum += a;
            const uint4 p = *(const uint4*)(g_feat16 + s * HD + lane * 8);
            const __half2* ph = (const __half2*)&p;
            float2 f0 = __half22float2(ph[0]);
            float2 f1 = __half22float2(ph[1]);
            float2 f2 = __half22float2(ph[2]);
            float2 f3 = __half22float2(ph[3]);
            acc[0] += a * f0.x; acc[1] += a * f0.y;
            acc[2] += a * f1.x; acc[3] += a * f1.y;
            acc[4] += a * f2.x; acc[5] += a * f2.y;
            acc[6] += a * f3.x; acc[7] += a * f3.y;
        }
    }
    const float inv = (ssum > 0.f) ? (1.f / ssum) : 0.f;

    const float4 b0 = *(const float4*)(b + lane * 8);
    const float4 b1 = *(const float4*)(b + lane * 8 + 4);
    float o0 = fmaxf(acc[0] * inv + b0.x, 0.f);
    float o1 = fmaxf(acc[1] * inv + b0.y, 0.f);
    float o2 = fmaxf(acc[2] * inv + b0.z, 0.f);
    float o3 = fmaxf(acc[3] * inv + b0.w, 0.f);
    float o4 = fmaxf(acc[4] * inv + b1.x, 0.f);
    float o5 = fmaxf(acc[5] * inv + b1.y, 0.f);
    float o6 = fmaxf(acc[6] * inv + b1.z, 0.f);
    float o7 = fmaxf(acc[7] * inv + b1.w, 0.f);

    __half2 p0 = __floats2half2_rn(o0, o1);
    __half2 p1 = __floats2half2_rn(o2, o3);
    __half2 p2 = __floats2half2_rn(o4, o5);
    __half2 p3 = __floats2half2_rn(o6, o7);
    uint4 pk;
    pk.x = *(uint32_t*)&p0; pk.y = *(uint32_t*)&p1;
    pk.z = *(uint32_t*)&p2; pk.w = *(uint32_t*)&p3;
    ((uint4*)(out + n * HD))[lane] = pk;
}

// ---------------- final dot scores (fp16 gather, fp32 accumulate) --------------
__global__ __launch_bounds__(256) void score_kernel(const int* __restrict__ src,
                                                    const int* __restrict__ dst,
                                                    const int* __restrict__ nsrc,
                                                    const int* __restrict__ ndst,
                                                    float* __restrict__ out) {
    int w = (blockIdx.x * blockDim.x + threadIdx.x) >> 5;
    int lane = threadIdx.x & 31;
    if (w >= 2 * EE) return;
    bool pos = w < EE;
    int e = pos ? w : w - EE;
    int uN = pos ? src[e] : nsrc[e];
    int vN = pos ? dst[e] : ndst[e];

    uint4 up = ((const uint4*)(g_hh + uN * HD))[lane];
    uint4 vp = ((const uint4*)(g_hh + vN * HD))[lane];
    float2 u0 = __half22float2(*(__half2*)&up.x), v0 = __half22float2(*(__half2*)&vp.x);
    float2 u1 = __half22float2(*(__half2*)&up.y), v1 = __half22float2(*(__half2*)&vp.y);
    float2 u2 = __half22float2(*(__half2*)&up.z), v2 = __half22float2(*(__half2*)&vp.z);
    float2 u3 = __half22float2(*(__half2*)&up.w), v3 = __half22float2(*(__half2*)&vp.w);
    float d = u0.x * v0.x + u0.y * v0.y + u1.x * v1.x + u1.y * v1.y +
              u2.x * v2.x + u2.y * v2.y + u3.x * v3.x + u3.y * v3.y;
#pragma unroll
    for (int off = 4; off >= 1; off >>= 1) d += __shfl_down_sync(0xffffffffu, d, off, 8);
    if ((lane & 7) == 0) {
        int h = lane >> 3;
        out[(pos ? 0 : EE * HH) + e * HH + h] = d;
    }
}

// ---------------- launch -------------------------------------------------------
extern "C" void kernel_launch(void* const* d_in, const int* in_sizes, int n_in,
                              void* d_out, int out_size) {
    const float* x    = (const float*)d_in[0];
    const int* src    = (const int*)d_in[1];
    const int* dst    = (const int*)d_in[2];
    const int* nsrc   = (const int*)d_in[3];
    const int* ndst   = (const int*)d_in[4];
    const float* W[3]  = {(const float*)d_in[5], (const float*)d_in[9],  (const float*)d_in[13]};
    const float* al[3] = {(const float*)d_in[6], (const float*)d_in[10], (const float*)d_in[14]};
    const float* ar[3] = {(const float*)d_in[7], (const float*)d_in[11], (const float*)d_in[15]};
    const float* bb[3] = {(const float*)d_in[8], (const float*)d_in[12], (const float*)d_in[16]};
    float* out = (float*)d_out;

    __half* actbuf = nullptr;
    cudaGetSymbolAddress((void**)&actbuf, g_act16);
    __half* featbuf = nullptr;
    cudaGetSymbolAddress((void**)&featbuf, g_feat16);
    __half* hhbuf = nullptr;
    cudaGetSymbolAddress((void**)&hhbuf, g_hh);
    __half* wbuf = nullptr;
    cudaGetSymbolAddress((void**)&wbuf, g_w16);
    int* cntbuf = nullptr;
    cudaGetSymbolAddress((void**)&cntbuf, g_cnt);

    // persistent side stream + fork/join events (created once, on the
    // uncaptured correctness call; reused identically during capture)
    static cudaStream_t s_side = nullptr;
    static cudaEvent_t s_fork = nullptr, s_join = nullptr;
    if (s_side == nullptr) {
        cudaStreamCreateWithFlags(&s_side, cudaStreamNonBlocking);
        cudaEventCreateWithFlags(&s_fork, cudaEventDisableTiming);
        cudaEventCreateWithFlags(&s_join, cudaEventDisableTiming);
    }

    const int scan_smem = NN * (int)sizeof(int);
    cudaFuncSetAttribute(csr_scan_kernel, cudaFuncAttributeMaxDynamicSharedMemorySize, scan_smem);

    dim3 gemm_grid((NN + 127) / 128, 2);
    const int cvt_blocks   = (NX4 + NW4 + 255) / 256;
    const int node_blocks  = (NN * 32 + 255) / 256;
    const int score_blocks = (2 * EE * 32 + 255) / 256;

    // ---- fork: CSR build chain on side stream, overlapped with cvt + gemm1 ----
    cudaEventRecord(s_fork, 0);
    cudaStreamWaitEvent(s_side, s_fork, 0);
    cudaMemsetAsync(cntbuf, 0, NN * sizeof(int), s_side);
    csr_hist_kernel<<<(EE + 255) / 256, 256, 0, s_side>>>(dst);
    csr_scan_kernel<<<1, 1024, scan_smem, s_side>>>();
    csr_scatter_kernel<<<(EE + 255) / 256, 256, 0, s_side>>>(src, dst);
    cudaEventRecord(s_join, s_side);

    // ---- main stream: converts + layer-1 GEMM (independent of CSR) ----
    cvt_all_kernel<<<cvt_blocks, 256>>>(x, W[0], W[1], W[2]);
    gemm_fused<<<gemm_grid, 256>>>(actbuf, wbuf, al[0], ar[0], featbuf);

    // ---- join before first CSR consumer ----
    cudaStreamWaitEvent(0, s_join, 0);

    fused_edge_kernel<<<node_blocks, 256>>>(bb[0], actbuf);
    for (int l = 1; l < 3; l++) {
        gemm_fused<<<gemm_grid, 256>>>(actbuf, wbuf + l * HD * HD, al[l], ar[l], featbuf);
        fused_edge_kernel<<<node_blocks, 256>>>(bb[l], (l == 2) ? hhbuf : actbuf);
    }
    score_kernel<<<score_blocks, 256>>>(src, dst, nsrc, ndst, out);
}

// round 11
// speedup vs baseline: 1.8104x; 1.0959x over previous
#include <cuda_runtime.h>
#include <cuda_fp16.h>
#include <math_constants.h>
#include <stdint.h>

#define NN 25000
#define EE 250000
#define HH 4
#define DD 64
#define HD 256   // H*D

// ---------------- scratch (device globals; no allocation allowed) -------------
__device__ __align__(16) __half g_act16[NN * HD];  // layer input (fp16)
__device__ __align__(16) __half g_feat16[NN * HD]; // x @ W (fp16)
__device__ __align__(16) __half g_hh[NN * HD];     // final output (score input)
__device__ __align__(16) __half g_w16[3 * HD * HD];
__device__ float g_elp[2 * NN * HH];
__device__ float g_erp[2 * NN * HH];
// pos CSR (by dst)
__device__ int g_cnt[NN];
__device__ int g_off[NN + 1];
__device__ int g_cur[NN];
__device__ int g_csr_src[EE];
__device__ int g_csr_eid[EE];
// neg CSR (by ndst) — used only by score
__device__ int g_ncnt[NN];
__device__ int g_noff[NN + 1];
__device__ int g_ncur[NN];
__device__ int2 g_ncsr[EE];    // (nsrc, eid)

// ---------------- helpers ----------------------------------------------------
__device__ __forceinline__ void mma_f16(float* d, const uint32_t* a, const uint32_t* b) {
    asm volatile(
        "mma.sync.aligned.m16n8k16.row.col.f32.f16.f16.f32 "
        "{%0,%1,%2,%3}, {%4,%5,%6,%7}, {%8,%9}, {%0,%1,%2,%3};"
        : "+f"(d[0]), "+f"(d[1]), "+f"(d[2]), "+f"(d[3])
        : "r"(a[0]), "r"(a[1]), "r"(a[2]), "r"(a[3]), "r"(b[0]), "r"(b[1]));
}

__device__ __forceinline__ uint32_t cvta_smem(const void* p) {
    return (uint32_t)__cvta_generic_to_shared(p);
}

#define CP_ASYNC16(dst, src, sz) \
    asm volatile("cp.async.cg.shared.global [%0], [%1], 16, %2;" :: "r"(dst), "l"(src), "r"(sz))
#define CP_COMMIT() asm volatile("cp.async.commit_group;")
template <int N>
__device__ __forceinline__ void cp_wait() {
    asm volatile("cp.async.wait_group %0;" :: "n"(N));
}

// ---------------- one-time fp32 -> fp16 converts (x and all W, one kernel) ----
#define NX4 (NN * HD / 4)
#define NW4 (3 * HD * HD / 4)
__global__ __launch_bounds__(256) void cvt_all_kernel(const float* __restrict__ x,
                                                      const float* __restrict__ W1,
                                                      const float* __restrict__ W2,
                                                      const float* __restrict__ W3) {
    int t = blockIdx.x * 256 + threadIdx.x;
    float4 v;
    uint2* dst;
    if (t < NX4) {
        v = ((const float4*)x)[t];
        dst = ((uint2*)g_act16) + t;
    } else {
        int u = t - NX4;
        if (u >= NW4) return;
        const float* src = (u < 16384) ? W1 : ((u < 32768) ? W2 : W3);
        v = ((const float4*)src)[u & 16383];
        dst = ((uint2*)g_w16) + u;
    }
    __half2 h0 = __floats2half2_rn(v.x, v.y);
    __half2 h1 = __floats2half2_rn(v.z, v.w);
    uint2 p; p.x = *(uint32_t*)&h0; p.y = *(uint32_t*)&h1;
    *dst = p;
}

// ---------------- CSR build ---------------------------------------------------
__global__ __launch_bounds__(256) void csr_hist_kernel(const int* __restrict__ dst,
                                                       int* __restrict__ cnt) {
    int i = blockIdx.x * blockDim.x + threadIdx.x;
    if (i < EE) atomicAdd(&cnt[dst[i]], 1);
}

// single block, 1024 threads, coalesced smem staging, shfl-based scan.
__global__ __launch_bounds__(1024) void csr_scan_kernel(const int* __restrict__ cnt,
                                                        int* __restrict__ off,
                                                        int* __restrict__ cur) {
    extern __shared__ int sm[];   // NN ints
    __shared__ int wsum[32];
    const int tid = threadIdx.x;
    const int lane = tid & 31, w = tid >> 5;

    for (int i = tid; i < NN; i += 1024) sm[i] = cnt[i];
    __syncthreads();

    const int base = tid * 25;
    int s = 0;
#pragma unroll
    for (int j = 0; j < 25; j++) {
        int idx = base + j;
        if (idx < NN) s += sm[idx];
    }
    int incl = s;
#pragma unroll
    for (int o = 1; o < 32; o <<= 1) {
        int v = __shfl_up_sync(0xffffffffu, incl, o);
        if (lane >= o) incl += v;
    }
    if (lane == 31) wsum[w] = incl;
    __syncthreads();
    if (w == 0) {
        int t = wsum[lane];
        int ti = t;
#pragma unroll
        for (int o = 1; o < 32; o <<= 1) {
            int v = __shfl_up_sync(0xffffffffu, ti, o);
            if (lane >= o) ti += v;
        }
        wsum[lane] = ti - t;
    }
    __syncthreads();
    int run = wsum[w] + (incl - s);

#pragma unroll
    for (int j = 0; j < 25; j++) {
        int idx = base + j;
        if (idx < NN) {
            int c = sm[idx];
            sm[idx] = run;
            run += c;
        }
    }
    __syncthreads();

    for (int i = tid; i < NN; i += 1024) {
        int o = sm[i];
        off[i] = o;
        cur[i] = o;
    }
    if (tid == 0) off[NN] = EE;
}

__global__ __launch_bounds__(256) void csr_scatter_pos(const int* __restrict__ src,
                                                       const int* __restrict__ dst) {
    int e = blockIdx.x * blockDim.x + threadIdx.x;
    if (e >= EE) return;
    int slot = atomicAdd(&g_cur[dst[e]], 1);
    g_csr_src[slot] = src[e];
    g_csr_eid[slot] = e;
}

__global__ __launch_bounds__(256) void csr_scatter_neg(const int* __restrict__ nsrc,
                                                       const int* __restrict__ ndst) {
    int e = blockIdx.x * blockDim.x + threadIdx.x;
    if (e >= EE) return;
    int slot = atomicAdd(&g_ncur[ndst[e]], 1);
    g_ncsr[slot] = make_int2(nsrc[e], e);
}

// ---------------- FP16 GEMM: cp.async + ldmatrix + fused el/er ----------------
#define BK 32
#define A_ROWB 80
#define B_ROWB 272
#define A_STAGEB (128 * A_ROWB)
#define B_STAGEB (BK * B_ROWB)

__global__ __launch_bounds__(256, 2) void gemm_fused(const __half* __restrict__ Ain,
                                                     const __half* __restrict__ Win,
                                                     const float* __restrict__ alp,
                                                     const float* __restrict__ arp,
                                                     __half* __restrict__ C16) {
    __shared__ __align__(16) char smem[2 * (A_STAGEB + B_STAGEB)];

    const int tid = threadIdx.x;
    const int bm = blockIdx.x * 128;
    const int bn = blockIdx.y * 128;
    const int lane = tid & 31;
    const int wid = tid >> 5;
    const int wm = (wid >> 2) * 64;
    const int wn = (wid & 3) * 32;
    const int g  = lane >> 2;
    const int c  = lane & 3;
    const int c2 = c * 2;

    const uint32_t smem_u32 = cvta_smem(smem);

    const int arow = tid >> 1, ach = (tid & 1) * 2;
    const bool aval = (bm + arow) < NN;
    const uint32_t asz = aval ? 16u : 0u;
    const __half* asrc0 = Ain + (size_t)(bm + arow) * 256 + ach * 8;
    const uint32_t adst0 = smem_u32 + arow * A_ROWB + ach * 16;
    const int bkrow = tid >> 3, bch = (tid & 7) * 2;
    const __half* bsrc0 = Win + (size_t)bkrow * 256 + bn + bch * 8;
    const uint32_t bdst0 = smem_u32 + 2 * A_STAGEB + bkrow * B_ROWB + bch * 16;

    const uint32_t a_lm0 = smem_u32 + (wm + (lane & 15)) * A_ROWB + (lane >> 4) * 16;
    const uint32_t b_lm0 = smem_u32 + 2 * A_STAGEB + (lane & 15) * B_ROWB
                         + ((wn >> 3) + (lane >> 4)) * 16;

    float acc[4][4][4];
#pragma unroll
    for (int i = 0; i < 4; i++)
#pragma unroll
        for (int j = 0; j < 4; j++)
#pragma unroll
            for (int t = 0; t < 4; t++) acc[i][j][t] = 0.f;

    CP_ASYNC16(adst0, asrc0, asz);
    CP_ASYNC16(adst0 + 16, asrc0 + 8, asz);
    CP_ASYNC16(bdst0, bsrc0, 16);
    CP_ASYNC16(bdst0 + 16, bsrc0 + 8, 16);
    CP_COMMIT();

    for (int kt = 0; kt < 8; kt++) {
        cp_wait<0>();
        __syncthreads();
        if (kt < 7) {
            const int nx = kt + 1, s = nx & 1;
            const __half* as = asrc0 + nx * BK;
            const __half* bs = bsrc0 + (size_t)nx * BK * 256;
            const uint32_t ad = adst0 + s * A_STAGEB;
            const uint32_t bd = bdst0 + s * B_STAGEB;
            CP_ASYNC16(ad, as, asz);
            CP_ASYNC16(ad + 16, as + 8, asz);
            CP_ASYNC16(bd, bs, 16);
            CP_ASYNC16(bd + 16, bs + 8, 16);
            CP_COMMIT();
        }
        const int s = kt & 1;
        const uint32_t aS = a_lm0 + s * A_STAGEB;
        const uint32_t bS = b_lm0 + s * B_STAGEB;
#pragma unroll
        for (int ks = 0; ks < 2; ks++) {
            uint32_t bfr[4][2];
#pragma unroll
            for (int jp = 0; jp < 2; jp++) {
                const uint32_t addr = bS + ks * (16 * B_ROWB) + jp * 32;
                asm volatile(
                    "ldmatrix.sync.aligned.m8n8.x4.trans.shared.b16 {%0,%1,%2,%3}, [%4];"
                    : "=r"(bfr[2*jp][0]), "=r"(bfr[2*jp][1]),
                      "=r"(bfr[2*jp+1][0]), "=r"(bfr[2*jp+1][1])
                    : "r"(addr));
            }
#pragma unroll
            for (int i = 0; i < 4; i++) {
                uint32_t afr[4];
                const uint32_t addr = aS + i * (16 * A_ROWB) + ks * 32;
                asm volatile(
                    "ldmatrix.sync.aligned.m8n8.x4.shared.b16 {%0,%1,%2,%3}, [%4];"
                    : "=r"(afr[0]), "=r"(afr[1]), "=r"(afr[2]), "=r"(afr[3])
                    : "r"(addr));
#pragma unroll
                for (int j = 0; j < 4; j++) mma_f16(acc[i][j], afr, bfr[j]);
            }
        }
    }

    // ---- epilogue: fp16 feat store + fused el/er partials ----
    const int colbase = bn + wn;
    const int hh_ = colbase >> 6;
    const int q_  = (colbase >> 5) & 1;
    float alv[4][2], arv[4][2];
#pragma unroll
    for (int j = 0; j < 4; j++) {
        int col = colbase + j * 8 + c2;
        alv[j][0] = alp[col];     alv[j][1] = alp[col + 1];
        arv[j][0] = arp[col];     arv[j][1] = arp[col + 1];
    }

#pragma unroll
    for (int i = 0; i < 4; i++) {
        const int r = bm + wm + i * 16 + g;
        float pel0 = 0.f, per0 = 0.f, pel1 = 0.f, per1 = 0.f;
#pragma unroll
        for (int j = 0; j < 4; j++) {
            const int col = colbase + j * 8 + c2;
            pel0 += acc[i][j][0] * alv[j][0] + acc[i][j][1] * alv[j][1];
            per0 += acc[i][j][0] * arv[j][0] + acc[i][j][1] * arv[j][1];
            pel1 += acc[i][j][2] * alv[j][0] + acc[i][j][3] * alv[j][1];
            per1 += acc[i][j][2] * arv[j][0] + acc[i][j][3] * arv[j][1];
            __half2 h01 = __floats2half2_rn(acc[i][j][0], acc[i][j][1]);
            __half2 h23 = __floats2half2_rn(acc[i][j][2], acc[i][j][3]);
            if (r < NN)     *(__half2*)(C16 + r * 256 + col)       = h01;
            if (r + 8 < NN) *(__half2*)(C16 + (r + 8) * 256 + col) = h23;
        }
#pragma unroll
        for (int o = 1; o <= 2; o <<= 1) {
            pel0 += __shfl_xor_sync(0xffffffffu, pel0, o);
            per0 += __shfl_xor_sync(0xffffffffu, per0, o);
            pel1 += __shfl_xor_sync(0xffffffffu, pel1, o);
            per1 += __shfl_xor_sync(0xffffffffu, per1, o);
        }
        if (c == 0) {
            if (r < NN) {
                g_elp[q_ * (NN * HH) + r * HH + hh_] = pel0;
                g_erp[q_ * (NN * HH) + r * HH + hh_] = per0;
            }
            if (r + 8 < NN) {
                g_elp[q_ * (NN * HH) + (r + 8) * HH + hh_] = pel1;
                g_erp[q_ * (NN * HH) + (r + 8) * HH + hh_] = per1;
            }
        }
    }
}

// ---------------- fused edge softmax + aggregation + bias/relu ----------------
__global__ __launch_bounds__(256) void fused_edge_kernel(const float* __restrict__ b,
                                                         __half* __restrict__ out) {
    const int n = (blockIdx.x * blockDim.x + threadIdx.x) >> 5;
    const int lane = threadIdx.x & 31;
    if (n >= NN) return;

    const int off = g_off[n];
    const int deg = g_off[n + 1] - off;
    const int h = lane >> 3;

    const float erh = g_erp[n * HH + h] + g_erp[NN * HH + n * HH + h];

    float acc[8];
#pragma unroll
    for (int j = 0; j < 8; j++) acc[j] = 0.f;
    float ssum = 0.f;

    for (int base = 0; base < deg; base += 32) {
        const int myi = base + lane;
        const int sv = (myi < deg) ? g_csr_src[off + myi] : 0;
        const int cnt = min(32, deg - base);
#pragma unroll 4
        for (int j = 0; j < cnt; j++) {
            const int s = __shfl_sync(0xffffffffu, sv, j);
            float e = g_elp[s * HH + h] + g_elp[NN * HH + s * HH + h] + erh;
            e = e > 0.f ? e : 0.2f * e;
            const float a = __expf(e);
            ssum += a;
            const uint4 p = *(const uint4*)(g_feat16 + s * HD + lane * 8);
            const __half2* ph = (const __half2*)&p;
            float2 f0 = __half22float2(ph[0]);
            float2 f1 = __half22float2(ph[1]);
            float2 f2 = __half22float2(ph[2]);
            float2 f3 = __half22float2(ph[3]);
            acc[0] += a * f0.x; acc[1] += a * f0.y;
            acc[2] += a * f1.x; acc[3] += a * f1.y;
            acc[4] += a * f2.x; acc[5] += a * f2.y;
            acc[6] += a * f3.x; acc[7] += a * f3.y;
        }
    }
    const float inv = (ssum > 0.f) ? (1.f / ssum) : 0.f;

    const float4 b0 = *(const float4*)(b + lane * 8);
    const float4 b1 = *(const float4*)(b + lane * 8 + 4);
    float o0 = fmaxf(acc[0] * inv + b0.x, 0.f);
    float o1 = fmaxf(acc[1] * inv + b0.y, 0.f);
    float o2 = fmaxf(acc[2] * inv + b0.z, 0.f);
    float o3 = fmaxf(acc[3] * inv + b0.w, 0.f);
    float o4 = fmaxf(acc[4] * inv + b1.x, 0.f);
    float o5 = fmaxf(acc[5] * inv + b1.y, 0.f);
    float o6 = fmaxf(acc[6] * inv + b1.z, 0.f);
    float o7 = fmaxf(acc[7] * inv + b1.w, 0.f);

    __half2 p0 = __floats2half2_rn(o0, o1);
    __half2 p1 = __floats2half2_rn(o2, o3);
    __half2 p2 = __floats2half2_rn(o4, o5);
    __half2 p3 = __floats2half2_rn(o6, o7);
    uint4 pk;
    pk.x = *(uint32_t*)&p0; pk.y = *(uint32_t*)&p1;
    pk.z = *(uint32_t*)&p2; pk.w = *(uint32_t*)&p3;
    ((uint4*)(out + n * HD))[lane] = pk;
}

// ---------------- CSR-structured dot scores ------------------------------------
// Warp per (node, pos/neg). Own row h[n] held in registers; gather only the
// counterpart rows. Identical lane partition + octet reduce as the old kernel
// -> bit-identical outputs, ~55% of the gather traffic.
__global__ __launch_bounds__(256) void score_kernel(float* __restrict__ out) {
    const int w = (blockIdx.x * blockDim.x + threadIdx.x) >> 5;
    const int lane = threadIdx.x & 31;
    if (w >= 2 * NN) return;
    const bool pos = w < NN;
    const int n = pos ? w : w - NN;

    const int* offp = pos ? g_off : g_noff;
    const int off = offp[n];
    const int deg = offp[n + 1] - off;
    if (deg == 0) return;

    const uint4 vp = ((const uint4*)(g_hh + n * HD))[lane];
    const __half2* vh = (const __half2*)&vp;
    const float2 v0 = __half22float2(vh[0]), v1 = __half22float2(vh[1]);
    const float2 v2 = __half22float2(vh[2]), v3 = __half22float2(vh[3]);

    float* obase = out + (pos ? 0 : EE * HH);

    for (int base = 0; base < deg; base += 32) {
        const int myi = base + lane;
        int sv = 0, ev = 0;
        if (myi < deg) {
            if (pos) { sv = g_csr_src[off + myi]; ev = g_csr_eid[off + myi]; }
            else     { int2 t = g_ncsr[off + myi]; sv = t.x; ev = t.y; }
        }
        const int cnt = min(32, deg - base);
        for (int j = 0; j < cnt; j++) {
            const int s  = __shfl_sync(0xffffffffu, sv, j);
            const int ei = __shfl_sync(0xffffffffu, ev, j);
            const uint4 up = *(const uint4*)(g_hh + s * HD + lane * 8);
            const __half2* uh = (const __half2*)&up;
            const float2 u0 = __half22float2(uh[0]), u1 = __half22float2(uh[1]);
            const float2 u2 = __half22float2(uh[2]), u3 = __half22float2(uh[3]);
            float d = u0.x * v0.x + u0.y * v0.y + u1.x * v1.x + u1.y * v1.y +
                      u2.x * v2.x + u2.y * v2.y + u3.x * v3.x + u3.y * v3.y;
#pragma unroll
            for (int o = 4; o >= 1; o >>= 1) d += __shfl_down_sync(0xffffffffu, d, o, 8);
            if ((lane & 7) == 0) obase[ei * HH + (lane >> 3)] = d;
        }
    }
}

// ---------------- launch -------------------------------------------------------
extern "C" void kernel_launch(void* const* d_in, const int* in_sizes, int n_in,
                              void* d_out, int out_size) {
    const float* x    = (const float*)d_in[0];
    const int* src    = (const int*)d_in[1];
    const int* dst    = (const int*)d_in[2];
    const int* nsrc   = (const int*)d_in[3];
    const int* ndst   = (const int*)d_in[4];
    const float* W[3]  = {(const float*)d_in[5], (const float*)d_in[9],  (const float*)d_in[13]};
    const float* al[3] = {(const float*)d_in[6], (const float*)d_in[10], (const float*)d_in[14]};
    const float* ar[3] = {(const float*)d_in[7], (const float*)d_in[11], (const float*)d_in[15]};
    const float* bb[3] = {(const float*)d_in[8], (const float*)d_in[12], (const float*)d_in[16]};
    float* out = (float*)d_out;

    __half* actbuf = nullptr;
    cudaGetSymbolAddress((void**)&actbuf, g_act16);
    __half* featbuf = nullptr;
    cudaGetSymbolAddress((void**)&featbuf, g_feat16);
    __half* hhbuf = nullptr;
    cudaGetSymbolAddress((void**)&hhbuf, g_hh);
    __half* wbuf = nullptr;
    cudaGetSymbolAddress((void**)&wbuf, g_w16);
    int* cntbuf = nullptr;
    cudaGetSymbolAddress((void**)&cntbuf, g_cnt);
    int* ncntbuf = nullptr;
    cudaGetSymbolAddress((void**)&ncntbuf, g_ncnt);
    int* offbuf = nullptr;
    cudaGetSymbolAddress((void**)&offbuf, g_off);
    int* curbuf = nullptr;
    cudaGetSymbolAddress((void**)&curbuf, g_cur);
    int* noffbuf = nullptr;
    cudaGetSymbolAddress((void**)&noffbuf, g_noff);
    int* ncurbuf = nullptr;
    cudaGetSymbolAddress((void**)&ncurbuf, g_ncur);

    static cudaStream_t s_side = nullptr;
    static cudaEvent_t s_fork = nullptr, s_join1 = nullptr, s_join2 = nullptr;
    if (s_side == nullptr) {
        cudaStreamCreateWithFlags(&s_side, cudaStreamNonBlocking);
        cudaEventCreateWithFlags(&s_fork, cudaEventDisableTiming);
        cudaEventCreateWithFlags(&s_join1, cudaEventDisableTiming);
        cudaEventCreateWithFlags(&s_join2, cudaEventDisableTiming);
    }

    const int scan_smem = NN * (int)sizeof(int);
    cudaFuncSetAttribute(csr_scan_kernel, cudaFuncAttributeMaxDynamicSharedMemorySize, scan_smem);

    dim3 gemm_grid((NN + 127) / 128, 2);
    const int cvt_blocks   = (NX4 + NW4 + 255) / 256;
    const int node_blocks  = (NN * 32 + 255) / 256;
    const int score_blocks = (2 * NN * 32 + 255) / 256;
    const int e_blocks     = (EE + 255) / 256;

    // ---- fork: CSR builds on side stream ----
    cudaEventRecord(s_fork, 0);
    cudaStreamWaitEvent(s_side, s_fork, 0);
    // pos CSR (gates fused_edge layer 1)
    cudaMemsetAsync(cntbuf, 0, NN * sizeof(int), s_side);
    csr_hist_kernel<<<e_blocks, 256, 0, s_side>>>(dst, cntbuf);
    csr_scan_kernel<<<1, 1024, scan_smem, s_side>>>(cntbuf, offbuf, curbuf);
    csr_scatter_pos<<<e_blocks, 256, 0, s_side>>>(src, dst);
    cudaEventRecord(s_join1, s_side);
    // neg CSR (gates only the final score kernel)
    cudaMemsetAsync(ncntbuf, 0, NN * sizeof(int), s_side);
    csr_hist_kernel<<<e_blocks, 256, 0, s_side>>>(ndst, ncntbuf);
    csr_scan_kernel<<<1, 1024, scan_smem, s_side>>>(ncntbuf, noffbuf, ncurbuf);
    csr_scatter_neg<<<e_blocks, 256, 0, s_side>>>(nsrc, ndst);
    cudaEventRecord(s_join2, s_side);

    // ---- main stream: converts + layer-1 GEMM (independent of CSR) ----
    cvt_all_kernel<<<cvt_blocks, 256>>>(x, W[0], W[1], W[2]);
    gemm_fused<<<gemm_grid, 256>>>(actbuf, wbuf, al[0], ar[0], featbuf);

    cudaStreamWaitEvent(0, s_join1, 0);
    fused_edge_kernel<<<node_blocks, 256>>>(bb[0], actbuf);
    for (int l = 1; l < 3; l++) {
        gemm_fused<<<gemm_grid, 256>>>(actbuf, wbuf + l * HD * HD, al[l], ar[l], featbuf);
        fused_edge_kernel<<<node_blocks, 256>>>(bb[l], (l == 2) ? hhbuf : actbuf);
    }
    cudaStreamWaitEvent(0, s_join2, 0);
    score_kernel<<<score_blocks, 256>>>(out);
}

// round 12
// speedup vs baseline: 1.8896x; 1.0438x over previous
#include <cuda_runtime.h>
#include <cuda_fp16.h>
#include <math_constants.h>
#include <stdint.h>

#define NN 25000
#define EE 250000
#define HH 4
#define DD 64
#define HD 256   // H*D

// ---------------- scratch (device globals; no allocation allowed) -------------
__device__ __align__(16) __half g_act16[NN * HD];  // layer input (fp16)
__device__ __align__(16) __half g_feat16[NN * HD]; // x @ W (fp16)
__device__ __align__(16) __half g_hh[NN * HD];     // final output (score input)
__device__ __align__(16) __half g_w16[3 * HD * HD];
__device__ float g_elp[2 * NN * HH];
__device__ float g_erp[2 * NN * HH];
// pos CSR (by dst)
__device__ int g_cnt[NN];
__device__ int g_off[NN + 1];
__device__ int g_cur[NN];
__device__ int g_csr_src[EE];
__device__ int g_csr_eid[EE];
// neg CSR (by ndst) — used only by score
__device__ int g_ncnt[NN];
__device__ int g_noff[NN + 1];
__device__ int g_ncur[NN];
__device__ int2 g_ncsr[EE];    // (nsrc, eid)

// ---------------- helpers ----------------------------------------------------
__device__ __forceinline__ void mma_f16(float* d, const uint32_t* a, const uint32_t* b) {
    asm volatile(
        "mma.sync.aligned.m16n8k16.row.col.f32.f16.f16.f32 "
        "{%0,%1,%2,%3}, {%4,%5,%6,%7}, {%8,%9}, {%0,%1,%2,%3};"
        : "+f"(d[0]), "+f"(d[1]), "+f"(d[2]), "+f"(d[3])
        : "r"(a[0]), "r"(a[1]), "r"(a[2]), "r"(a[3]), "r"(b[0]), "r"(b[1]));
}

__device__ __forceinline__ uint32_t cvta_smem(const void* p) {
    return (uint32_t)__cvta_generic_to_shared(p);
}

#define CP_ASYNC16(dst, src, sz) \
    asm volatile("cp.async.cg.shared.global [%0], [%1], 16, %2;" :: "r"(dst), "l"(src), "r"(sz))
#define CP_COMMIT() asm volatile("cp.async.commit_group;")
template <int N>
__device__ __forceinline__ void cp_wait() {
    asm volatile("cp.async.wait_group %0;" :: "n"(N));
}

// ---------------- one-time fp32 -> fp16 converts (x and all W, one kernel) ----
#define NX4 (NN * HD / 4)
#define NW4 (3 * HD * HD / 4)
__global__ __launch_bounds__(256) void cvt_all_kernel(const float* __restrict__ x,
                                                      const float* __restrict__ W1,
                                                      const float* __restrict__ W2,
                                                      const float* __restrict__ W3) {
    int t = blockIdx.x * 256 + threadIdx.x;
    float4 v;
    uint2* dst;
    if (t < NX4) {
        v = ((const float4*)x)[t];
        dst = ((uint2*)g_act16) + t;
    } else {
        int u = t - NX4;
        if (u >= NW4) return;
        const float* src = (u < 16384) ? W1 : ((u < 32768) ? W2 : W3);
        v = ((const float4*)src)[u & 16383];
        dst = ((uint2*)g_w16) + u;
    }
    __half2 h0 = __floats2half2_rn(v.x, v.y);
    __half2 h1 = __floats2half2_rn(v.z, v.w);
    uint2 p; p.x = *(uint32_t*)&h0; p.y = *(uint32_t*)&h1;
    *dst = p;
}

// ---------------- CSR build ---------------------------------------------------
__global__ __launch_bounds__(256) void csr_hist_kernel(const int* __restrict__ dst,
                                                       int* __restrict__ cnt) {
    int i = blockIdx.x * blockDim.x + threadIdx.x;
    if (i < EE) atomicAdd(&cnt[dst[i]], 1);
}

__global__ __launch_bounds__(1024) void csr_scan_kernel(const int* __restrict__ cnt,
                                                        int* __restrict__ off,
                                                        int* __restrict__ cur) {
    extern __shared__ int sm[];   // NN ints
    __shared__ int wsum[32];
    const int tid = threadIdx.x;
    const int lane = tid & 31, w = tid >> 5;

    for (int i = tid; i < NN; i += 1024) sm[i] = cnt[i];
    __syncthreads();

    const int base = tid * 25;
    int s = 0;
#pragma unroll
    for (int j = 0; j < 25; j++) {
        int idx = base + j;
        if (idx < NN) s += sm[idx];
    }
    int incl = s;
#pragma unroll
    for (int o = 1; o < 32; o <<= 1) {
        int v = __shfl_up_sync(0xffffffffu, incl, o);
        if (lane >= o) incl += v;
    }
    if (lane == 31) wsum[w] = incl;
    __syncthreads();
    if (w == 0) {
        int t = wsum[lane];
        int ti = t;
#pragma unroll
        for (int o = 1; o < 32; o <<= 1) {
            int v = __shfl_up_sync(0xffffffffu, ti, o);
            if (lane >= o) ti += v;
        }
        wsum[lane] = ti - t;
    }
    __syncthreads();
    int run = wsum[w] + (incl - s);

#pragma unroll
    for (int j = 0; j < 25; j++) {
        int idx = base + j;
        if (idx < NN) {
            int c = sm[idx];
            sm[idx] = run;
            run += c;
        }
    }
    __syncthreads();

    for (int i = tid; i < NN; i += 1024) {
        int o = sm[i];
        off[i] = o;
        cur[i] = o;
    }
    if (tid == 0) off[NN] = EE;
}

__global__ __launch_bounds__(256) void csr_scatter_pos(const int* __restrict__ src,
                                                       const int* __restrict__ dst) {
    int e = blockIdx.x * blockDim.x + threadIdx.x;
    if (e >= EE) return;
    int slot = atomicAdd(&g_cur[dst[e]], 1);
    g_csr_src[slot] = src[e];
    g_csr_eid[slot] = e;
}

__global__ __launch_bounds__(256) void csr_scatter_neg(const int* __restrict__ nsrc,
                                                       const int* __restrict__ ndst) {
    int e = blockIdx.x * blockDim.x + threadIdx.x;
    if (e >= EE) return;
    int slot = atomicAdd(&g_ncur[ndst[e]], 1);
    g_ncsr[slot] = make_int2(nsrc[e], e);
}

// ---------------- FP16 GEMM: cp.async + ldmatrix + fused el/er ----------------
// Tile M=192, N=128, BK=32. grid (131, 2) = 262 CTAs -> single wave at 2/SM.
// 8 warps as 2m x 4n: warp tile 96x32 (6 x 4 m16n8k16 atoms).
#define BK 32
#define MT 192
#define A_ROWB 80
#define B_ROWB 272
#define A_STAGEB (MT * A_ROWB)    // 15360
#define B_STAGEB (BK * B_ROWB)    // 8704

__global__ __launch_bounds__(256, 2) void gemm_fused(const __half* __restrict__ Ain,
                                                     const __half* __restrict__ Win,
                                                     const float* __restrict__ alp,
                                                     const float* __restrict__ arp,
                                                     __half* __restrict__ C16) {
    __shared__ __align__(16) char smem[2 * (A_STAGEB + B_STAGEB)];

    const int tid = threadIdx.x;
    const int bm = blockIdx.x * MT;
    const int bn = blockIdx.y * 128;
    const int lane = tid & 31;
    const int wid = tid >> 5;
    const int wm = (wid >> 2) * 96;   // 0 / 96
    const int wn = (wid & 3) * 32;
    const int g  = lane >> 2;
    const int c  = lane & 3;
    const int c2 = c * 2;

    const uint32_t smem_u32 = cvta_smem(smem);

    // --- A producer: 3 rows per thread (r, r+64, r+128), one 16B chunk each ---
    const int arow = tid >> 2;              // 0..63
    const int acol = (tid & 3) * 8;         // half offset in row (0/8/16/24)
    const uint32_t asz0 = (bm + arow)       < NN ? 16u : 0u;
    const uint32_t asz1 = (bm + arow + 64)  < NN ? 16u : 0u;
    const uint32_t asz2 = (bm + arow + 128) < NN ? 16u : 0u;
    const __half* asrc0 = Ain + (size_t)(bm + arow) * 256 + acol;
    const __half* asrc1 = asrc0 + (size_t)64 * 256;
    const __half* asrc2 = asrc0 + (size_t)128 * 256;
    const uint32_t adst0 = smem_u32 + arow * A_ROWB + (tid & 3) * 16;
    const uint32_t adst1 = adst0 + 64 * A_ROWB;
    const uint32_t adst2 = adst0 + 128 * A_ROWB;
    // --- B producer: unchanged ---
    const int bkrow = tid >> 3, bch = (tid & 7) * 2;
    const __half* bsrc0 = Win + (size_t)bkrow * 256 + bn + bch * 8;
    const uint32_t bdst0 = smem_u32 + 2 * A_STAGEB + bkrow * B_ROWB + bch * 16;

    const uint32_t a_lm0 = smem_u32 + (wm + (lane & 15)) * A_ROWB + (lane >> 4) * 16;
    const uint32_t b_lm0 = smem_u32 + 2 * A_STAGEB + (lane & 15) * B_ROWB
                         + ((wn >> 3) + (lane >> 4)) * 16;

    float acc[6][4][4];
#pragma unroll
    for (int i = 0; i < 6; i++)
#pragma unroll
        for (int j = 0; j < 4; j++)
#pragma unroll
            for (int t = 0; t < 4; t++) acc[i][j][t] = 0.f;

    CP_ASYNC16(adst0, asrc0, asz0);
    CP_ASYNC16(adst1, asrc1, asz1);
    CP_ASYNC16(adst2, asrc2, asz2);
    CP_ASYNC16(bdst0, bsrc0, 16);
    CP_ASYNC16(bdst0 + 16, bsrc0 + 8, 16);
    CP_COMMIT();

    for (int kt = 0; kt < 8; kt++) {
        cp_wait<0>();
        __syncthreads();
        if (kt < 7) {
            const int nx = kt + 1, s = nx & 1;
            const int ko = nx * BK;
            const uint32_t ao = s * A_STAGEB;
            CP_ASYNC16(adst0 + ao, asrc0 + ko, asz0);
            CP_ASYNC16(adst1 + ao, asrc1 + ko, asz1);
            CP_ASYNC16(adst2 + ao, asrc2 + ko, asz2);
            const __half* bs = bsrc0 + (size_t)ko * 256;
            const uint32_t bd = bdst0 + s * B_STAGEB;
            CP_ASYNC16(bd, bs, 16);
            CP_ASYNC16(bd + 16, bs + 8, 16);
            CP_COMMIT();
        }
        const int s = kt & 1;
        const uint32_t aS = a_lm0 + s * A_STAGEB;
        const uint32_t bS = b_lm0 + s * B_STAGEB;
#pragma unroll
        for (int ks = 0; ks < 2; ks++) {
            uint32_t bfr[4][2];
#pragma unroll
            for (int jp = 0; jp < 2; jp++) {
                const uint32_t addr = bS + ks * (16 * B_ROWB) + jp * 32;
                asm volatile(
                    "ldmatrix.sync.aligned.m8n8.x4.trans.shared.b16 {%0,%1,%2,%3}, [%4];"
                    : "=r"(bfr[2*jp][0]), "=r"(bfr[2*jp][1]),
                      "=r"(bfr[2*jp+1][0]), "=r"(bfr[2*jp+1][1])
                    : "r"(addr));
            }
#pragma unroll
            for (int i = 0; i < 6; i++) {
                uint32_t afr[4];
                const uint32_t addr = aS + i * (16 * A_ROWB) + ks * 32;
                asm volatile(
                    "ldmatrix.sync.aligned.m8n8.x4.shared.b16 {%0,%1,%2,%3}, [%4];"
                    : "=r"(afr[0]), "=r"(afr[1]), "=r"(afr[2]), "=r"(afr[3])
                    : "r"(addr));
#pragma unroll
                for (int j = 0; j < 4; j++) mma_f16(acc[i][j], afr, bfr[j]);
            }
        }
    }

    // ---- epilogue: fp16 feat store + fused el/er partials ----
    const int colbase = bn + wn;
    const int hh_ = colbase >> 6;
    const int q_  = (colbase >> 5) & 1;
    float alv[4][2], arv[4][2];
#pragma unroll
    for (int j = 0; j < 4; j++) {
        int col = colbase + j * 8 + c2;
        alv[j][0] = alp[col];     alv[j][1] = alp[col + 1];
        arv[j][0] = arp[col];     arv[j][1] = arp[col + 1];
    }

#pragma unroll
    for (int i = 0; i < 6; i++) {
        const int r = bm + wm + i * 16 + g;
        float pel0 = 0.f, per0 = 0.f, pel1 = 0.f, per1 = 0.f;
#pragma unroll
        for (int j = 0; j < 4; j++) {
            const int col = colbase + j * 8 + c2;
            pel0 += acc[i][j][0] * alv[j][0] + acc[i][j][1] * alv[j][1];
            per0 += acc[i][j][0] * arv[j][0] + acc[i][j][1] * arv[j][1];
            pel1 += acc[i][j][2] * alv[j][0] + acc[i][j][3] * alv[j][1];
            per1 += acc[i][j][2] * arv[j][0] + acc[i][j][3] * arv[j][1];
            __half2 h01 = __floats2half2_rn(acc[i][j][0], acc[i][j][1]);
            __half2 h23 = __floats2half2_rn(acc[i][j][2], acc[i][j][3]);
            if (r < NN)     *(__half2*)(C16 + r * 256 + col)       = h01;
            if (r + 8 < NN) *(__half2*)(C16 + (r + 8) * 256 + col) = h23;
        }
#pragma unroll
        for (int o = 1; o <= 2; o <<= 1) {
            pel0 += __shfl_xor_sync(0xffffffffu, pel0, o);
            per0 += __shfl_xor_sync(0xffffffffu, per0, o);
            pel1 += __shfl_xor_sync(0xffffffffu, pel1, o);
            per1 += __shfl_xor_sync(0xffffffffu, per1, o);
        }
        if (c == 0) {
            if (r < NN) {
                g_elp[q_ * (NN * HH) + r * HH + hh_] = pel0;
                g_erp[q_ * (NN * HH) + r * HH + hh_] = per0;
            }
            if (r + 8 < NN) {
                g_elp[q_ * (NN * HH) + (r + 8) * HH + hh_] = pel1;
                g_erp[q_ * (NN * HH) + (r + 8) * HH + hh_] = per1;
            }
        }
    }
}

// ---------------- fused edge softmax + aggregation + bias/relu ----------------
__global__ __launch_bounds__(256) void fused_edge_kernel(const float* __restrict__ b,
                                                         __half* __restrict__ out) {
    const int n = (blockIdx.x * blockDim.x + threadIdx.x) >> 5;
    const int lane = threadIdx.x & 31;
    if (n >= NN) return;

    const int off = g_off[n];
    const int deg = g_off[n + 1] - off;
    const int h = lane >> 3;

    const float erh = g_erp[n * HH + h] + g_erp[NN * HH + n * HH + h];

    float acc[8];
#pragma unroll
    for (int j = 0; j < 8; j++) acc[j] = 0.f;
    float ssum = 0.f;

    for (int base = 0; base < deg; base += 32) {
        const int myi = base + lane;
        const int sv = (myi < deg) ? g_csr_src[off + myi] : 0;
        const int cnt = min(32, deg - base);
#pragma unroll 4
        for (int j = 0; j < cnt; j++) {
            const int s = __shfl_sync(0xffffffffu, sv, j);
            float e = g_elp[s * HH + h] + g_elp[NN * HH + s * HH + h] + erh;
            e = e > 0.f ? e : 0.2f * e;
            const float a = __expf(e);
            ssum += a;
            const uint4 p = *(const uint4*)(g_feat16 + s * HD + lane * 8);
            const __half2* ph = (const __half2*)&p;
            float2 f0 = __half22float2(ph[0]);
            float2 f1 = __half22float2(ph[1]);
            float2 f2 = __half22float2(ph[2]);
            float2 f3 = __half22float2(ph[3]);
            acc[0] += a * f0.x; acc[1] += a * f0.y;
            acc[2] += a * f1.x; acc[3] += a * f1.y;
            acc[4] += a * f2.x; acc[5] += a * f2.y;
            acc[6] += a * f3.x; acc[7] += a * f3.y;
        }
    }
    const float inv = (ssum > 0.f) ? (1.f / ssum) : 0.f;

    const float4 b0 = *(const float4*)(b + lane * 8);
    const float4 b1 = *(const float4*)(b + lane * 8 + 4);
    float o0 = fmaxf(acc[0] * inv + b0.x, 0.f);
    float o1 = fmaxf(acc[1] * inv + b0.y, 0.f);
    float o2 = fmaxf(acc[2] * inv + b0.z, 0.f);
    float o3 = fmaxf(acc[3] * inv + b0.w, 0.f);
    float o4 = fmaxf(acc[4] * inv + b1.x, 0.f);
    float o5 = fmaxf(acc[5] * inv + b1.y, 0.f);
    float o6 = fmaxf(acc[6] * inv + b1.z, 0.f);
    float o7 = fmaxf(acc[7] * inv + b1.w, 0.f);

    __half2 p0 = __floats2half2_rn(o0, o1);
    __half2 p1 = __floats2half2_rn(o2, o3);
    __half2 p2 = __floats2half2_rn(o4, o5);
    __half2 p3 = __floats2half2_rn(o6, o7);
    uint4 pk;
    pk.x = *(uint32_t*)&p0; pk.y = *(uint32_t*)&p1;
    pk.z = *(uint32_t*)&p2; pk.w = *(uint32_t*)&p3;
    ((uint4*)(out + n * HD))[lane] = pk;
}

// ---------------- CSR-structured dot scores ------------------------------------
__global__ __launch_bounds__(256) void score_kernel(float* __restrict__ out) {
    const int w = (blockIdx.x * blockDim.x + threadIdx.x) >> 5;
    const int lane = threadIdx.x & 31;
    if (w >= 2 * NN) return;
    const bool pos = w < NN;
    const int n = pos ? w : w - NN;

    const int* offp = pos ? g_off : g_noff;
    const int off = offp[n];
    const int deg = offp[n + 1] - off;
    if (deg == 0) return;

    const uint4 vp = ((const uint4*)(g_hh + n * HD))[lane];
    const __half2* vh = (const __half2*)&vp;
    const float2 v0 = __half22float2(vh[0]), v1 = __half22float2(vh[1]);
    const float2 v2 = __half22float2(vh[2]), v3 = __half22float2(vh[3]);

    float* obase = out + (pos ? 0 : EE * HH);

    for (int base = 0; base < deg; base += 32) {
        const int myi = base + lane;
        int sv = 0, ev = 0;
        if (myi < deg) {
            if (pos) { sv = g_csr_src[off + myi]; ev = g_csr_eid[off + myi]; }
            else     { int2 t = g_ncsr[off + myi]; sv = t.x; ev = t.y; }
        }
        const int cnt = min(32, deg - base);
        for (int j = 0; j < cnt; j++) {
            const int s  = __shfl_sync(0xffffffffu, sv, j);
            const int ei = __shfl_sync(0xffffffffu, ev, j);
            const uint4 up = *(const uint4*)(g_hh + s * HD + lane * 8);
            const __half2* uh = (const __half2*)&up;
            const float2 u0 = __half22float2(uh[0]), u1 = __half22float2(uh[1]);
            const float2 u2 = __half22float2(uh[2]), u3 = __half22float2(uh[3]);
            float d = u0.x * v0.x + u0.y * v0.y + u1.x * v1.x + u1.y * v1.y +
                      u2.x * v2.x + u2.y * v2.y + u3.x * v3.x + u3.y * v3.y;
#pragma unroll
            for (int o = 4; o >= 1; o >>= 1) d += __shfl_down_sync(0xffffffffu, d, o, 8);
            if ((lane & 7) == 0) obase[ei * HH + (lane >> 3)] = d;
        }
    }
}

// ---------------- launch -------------------------------------------------------
extern "C" void kernel_launch(void* const* d_in, const int* in_sizes, int n_in,
                              void* d_out, int out_size) {
    const float* x    = (const float*)d_in[0];
    const int* src    = (const int*)d_in[1];
    const int* dst    = (const int*)d_in[2];
    const int* nsrc   = (const int*)d_in[3];
    const int* ndst   = (const int*)d_in[4];
    const float* W[3]  = {(const float*)d_in[5], (const float*)d_in[9],  (const float*)d_in[13]};
    const float* al[3] = {(const float*)d_in[6], (const float*)d_in[10], (const float*)d_in[14]};
    const float* ar[3] = {(const float*)d_in[7], (const float*)d_in[11], (const float*)d_in[15]};
    const float* bb[3] = {(const float*)d_in[8], (const float*)d_in[12], (const float*)d_in[16]};
    float* out = (float*)d_out;

    __half* actbuf = nullptr;
    cudaGetSymbolAddress((void**)&actbuf, g_act16);
    __half* featbuf = nullptr;
    cudaGetSymbolAddress((void**)&featbuf, g_feat16);
    __half* hhbuf = nullptr;
    cudaGetSymbolAddress((void**)&hhbuf, g_hh);
    __half* wbuf = nullptr;
    cudaGetSymbolAddress((void**)&wbuf, g_w16);
    int* cntbuf = nullptr;
    cudaGetSymbolAddress((void**)&cntbuf, g_cnt);
    int* ncntbuf = nullptr;
    cudaGetSymbolAddress((void**)&ncntbuf, g_ncnt);
    int* offbuf = nullptr;
    cudaGetSymbolAddress((void**)&offbuf, g_off);
    int* curbuf = nullptr;
    cudaGetSymbolAddress((void**)&curbuf, g_cur);
    int* noffbuf = nullptr;
    cudaGetSymbolAddress((void**)&noffbuf, g_noff);
    int* ncurbuf = nullptr;
    cudaGetSymbolAddress((void**)&ncurbuf, g_ncur);

    static cudaStream_t s_side = nullptr;
    static cudaEvent_t s_fork = nullptr, s_join1 = nullptr, s_join2 = nullptr;
    if (s_side == nullptr) {
        cudaStreamCreateWithFlags(&s_side, cudaStreamNonBlocking);
        cudaEventCreateWithFlags(&s_fork, cudaEventDisableTiming);
        cudaEventCreateWithFlags(&s_join1, cudaEventDisableTiming);
        cudaEventCreateWithFlags(&s_join2, cudaEventDisableTiming);
    }

    const int scan_smem = NN * (int)sizeof(int);
    cudaFuncSetAttribute(csr_scan_kernel, cudaFuncAttributeMaxDynamicSharedMemorySize, scan_smem);

    dim3 gemm_grid((NN + MT - 1) / MT, 2);   // (131, 2) = 262 CTAs: single wave
    const int cvt_blocks   = (NX4 + NW4 + 255) / 256;
    const int node_blocks  = (NN * 32 + 255) / 256;
    const int score_blocks = (2 * NN * 32 + 255) / 256;
    const int e_blocks     = (EE + 255) / 256;

    // ---- fork: CSR builds on side stream ----
    cudaEventRecord(s_fork, 0);
    cudaStreamWaitEvent(s_side, s_fork, 0);
    cudaMemsetAsync(cntbuf, 0, NN * sizeof(int), s_side);
    csr_hist_kernel<<<e_blocks, 256, 0, s_side>>>(dst, cntbuf);
    csr_scan_kernel<<<1, 1024, scan_smem, s_side>>>(cntbuf, offbuf, curbuf);
    csr_scatter_pos<<<e_blocks, 256, 0, s_side>>>(src, dst);
    cudaEventRecord(s_join1, s_side);
    cudaMemsetAsync(ncntbuf, 0, NN * sizeof(int), s_side);
    csr_hist_kernel<<<e_blocks, 256, 0, s_side>>>(ndst, ncntbuf);
    csr_scan_kernel<<<1, 1024, scan_smem, s_side>>>(ncntbuf, noffbuf, ncurbuf);
    csr_scatter_neg<<<e_blocks, 256, 0, s_side>>>(nsrc, ndst);
    cudaEventRecord(s_join2, s_side);

    // ---- main stream: converts + layer-1 GEMM (independent of CSR) ----
    cvt_all_kernel<<<cvt_blocks, 256>>>(x, W[0], W[1], W[2]);
    gemm_fused<<<gemm_grid, 256>>>(actbuf, wbuf, al[0], ar[0], featbuf);

    cudaStreamWaitEvent(0, s_join1, 0);
    fused_edge_kernel<<<node_blocks, 256>>>(bb[0], actbuf);
    for (int l = 1; l < 3; l++) {
        gemm_fused<<<gemm_grid, 256>>>(actbuf, wbuf + l * HD * HD, al[l], ar[l], featbuf);
        fused_edge_kernel<<<node_blocks, 256>>>(bb[l], (l == 2) ? hhbuf : actbuf);
    }
    cudaStreamWaitEvent(0, s_join2, 0);
    score_kernel<<<score_blocks, 256>>>(out);
}